// round 1
// baseline (speedup 1.0000x reference)
#include <cuda_runtime.h>
#include <math.h>

// Problem constants
#define Bn  2
#define Sn  2048
#define Dn  1024
#define Hn  16
#define DHn 64
#define BHn (Bn*Hn)

// ---------------------------------------------------------------------------
// Scratch (static __device__ — no runtime allocation, per harness rules)
// ---------------------------------------------------------------------------
__device__ float g_Q [(size_t)Bn*Sn*Dn];        // 16.8 MB
__device__ float g_K [(size_t)Bn*Sn*Dn];
__device__ float g_V [(size_t)Bn*Sn*Dn];
__device__ float g_KR[(size_t)Sn*Dn];           //  8.4 MB
__device__ float g_T [(size_t)BHn*Sn*Sn];       // 536 MB : T = Q @ KR^T per (b,h)
__device__ float g_AO[(size_t)Bn*Sn*Dn];        // attention output before Wo

// ---------------------------------------------------------------------------
// 128x128x8 SGEMM, C = A@W + bias.  A:[M,K] W:[K,N] row-major. 256 thr, 8x8 micro
// ---------------------------------------------------------------------------
__global__ __launch_bounds__(256, 2)
void gemm_nn_bias(const float* __restrict__ A, const float* __restrict__ W,
                  const float* __restrict__ bias, float* __restrict__ C,
                  int M, int N, int K)
{
    __shared__ float As[8][132];   // transposed A tile, padded (conflict-free)
    __shared__ float Bs[8][132];
    const int t  = threadIdx.x;
    const int tx = t & 15, ty = t >> 4;
    const int row0 = blockIdx.y << 7, col0 = blockIdx.x << 7;
    const int ar = t >> 1,  ak = (t & 1) << 2;      // A tile: 128 rows x 8 k
    const int bk = t >> 5,  bc = (t & 31) << 2;     // B tile: 8 k x 128 cols

    float acc[8][8];
#pragma unroll
    for (int i = 0; i < 8; i++)
#pragma unroll
        for (int j = 0; j < 8; j++) acc[i][j] = 0.f;

    const float* Ap = A + (size_t)(row0 + ar) * K + ak;
    const float* Wp = W + (size_t)bk * N + col0 + bc;

    for (int k0 = 0; k0 < K; k0 += 8) {
        float4 a4 = *(const float4*)(Ap + k0);
        As[ak + 0][ar] = a4.x; As[ak + 1][ar] = a4.y;
        As[ak + 2][ar] = a4.z; As[ak + 3][ar] = a4.w;
        *(float4*)&Bs[bk][bc] = *(const float4*)(Wp + (size_t)k0 * N);
        __syncthreads();
#pragma unroll
        for (int kk = 0; kk < 8; kk++) {
            float4 a0 = *(const float4*)&As[kk][ty << 3];
            float4 a1 = *(const float4*)&As[kk][(ty << 3) + 4];
            float4 b0 = *(const float4*)&Bs[kk][tx << 3];
            float4 b1 = *(const float4*)&Bs[kk][(tx << 3) + 4];
            float av[8] = {a0.x,a0.y,a0.z,a0.w,a1.x,a1.y,a1.z,a1.w};
            float bv[8] = {b0.x,b0.y,b0.z,b0.w,b1.x,b1.y,b1.z,b1.w};
#pragma unroll
            for (int i = 0; i < 8; i++)
#pragma unroll
                for (int j = 0; j < 8; j++)
                    acc[i][j] = fmaf(av[i], bv[j], acc[i][j]);
        }
        __syncthreads();
    }
    float4 bb0 = *(const float4*)(bias + col0 + (tx << 3));
    float4 bb1 = *(const float4*)(bias + col0 + (tx << 3) + 4);
#pragma unroll
    for (int i = 0; i < 8; i++) {
        float* Cp = C + (size_t)(row0 + (ty << 3) + i) * N + col0 + (tx << 3);
        float4 o0 = make_float4(acc[i][0]+bb0.x, acc[i][1]+bb0.y,
                                acc[i][2]+bb0.z, acc[i][3]+bb0.w);
        float4 o1 = make_float4(acc[i][4]+bb1.x, acc[i][5]+bb1.y,
                                acc[i][6]+bb1.z, acc[i][7]+bb1.w);
        *(float4*)Cp       = o0;
        *(float4*)(Cp + 4) = o1;
    }
}

// ---------------------------------------------------------------------------
// T[bh] = Q_bh [S,64] @ KR_h^T [64,S]   (NT GEMM, K=64)
// ---------------------------------------------------------------------------
__global__ __launch_bounds__(256, 2)
void gemm_t_kernel()
{
    __shared__ float As[8][132];
    __shared__ float Bs[8][132];
    const int t  = threadIdx.x;
    const int tx = t & 15, ty = t >> 4;
    const int bh = blockIdx.z, b = bh >> 4, h = bh & 15;
    const int row0 = blockIdx.y << 7, col0 = blockIdx.x << 7;
    const int ar = t >> 1, ak = (t & 1) << 2;

    const float* A  = g_Q  + (size_t)b * Sn * Dn + h * DHn;   // lda = Dn
    const float* Bm = g_KR + h * DHn;                         // ldb = Dn
    float* C = g_T + (size_t)bh * Sn * Sn;

    float acc[8][8];
#pragma unroll
    for (int i = 0; i < 8; i++)
#pragma unroll
        for (int j = 0; j < 8; j++) acc[i][j] = 0.f;

    for (int k0 = 0; k0 < DHn; k0 += 8) {
        float4 a4 = *(const float4*)(A  + (size_t)(row0 + ar) * Dn + k0 + ak);
        As[ak+0][ar]=a4.x; As[ak+1][ar]=a4.y; As[ak+2][ar]=a4.z; As[ak+3][ar]=a4.w;
        float4 b4 = *(const float4*)(Bm + (size_t)(col0 + ar) * Dn + k0 + ak);
        Bs[ak+0][ar]=b4.x; Bs[ak+1][ar]=b4.y; Bs[ak+2][ar]=b4.z; Bs[ak+3][ar]=b4.w;
        __syncthreads();
#pragma unroll
        for (int kk = 0; kk < 8; kk++) {
            float4 a0 = *(const float4*)&As[kk][ty << 3];
            float4 a1 = *(const float4*)&As[kk][(ty << 3) + 4];
            float4 b0 = *(const float4*)&Bs[kk][tx << 3];
            float4 b1 = *(const float4*)&Bs[kk][(tx << 3) + 4];
            float av[8] = {a0.x,a0.y,a0.z,a0.w,a1.x,a1.y,a1.z,a1.w};
            float bv[8] = {b0.x,b0.y,b0.z,b0.w,b1.x,b1.y,b1.z,b1.w};
#pragma unroll
            for (int i = 0; i < 8; i++)
#pragma unroll
                for (int j = 0; j < 8; j++)
                    acc[i][j] = fmaf(av[i], bv[j], acc[i][j]);
        }
        __syncthreads();
    }
#pragma unroll
    for (int i = 0; i < 8; i++) {
        float* Cp = C + (size_t)(row0 + (ty << 3) + i) * Sn + col0 + (tx << 3);
        *(float4*)Cp       = make_float4(acc[i][0],acc[i][1],acc[i][2],acc[i][3]);
        *(float4*)(Cp + 4) = make_float4(acc[i][4],acc[i][5],acc[i][6],acc[i][7]);
    }
}

// ---------------------------------------------------------------------------
// Fused flash attention with relative-shift gather.
//   score(i,j) = ((q_i+u_h)·k_j + BD(i,j)) * 1/8,  softmax over j, @V
//   BD(i,j): j<=i -> T[i][S-1-i+j] ; j==i+1 -> 0 ; j>i+1 -> T[i+1][j-i-2]
//   (GH term is per-row constant -> softmax-invariant -> dropped)
// One block: 64 query rows x all 2048 keys (tiles of 64). 256 threads.
// ---------------------------------------------------------------------------
#define QP 68   // padded pitch for Qs/Ks  (float4-aligned, conflict-mitigating)
#define PP 65   // padded pitch for Ps
#define FLASH_SMEM ((64*QP*2 + 64*64 + 64*PP + 64*16 + 128) * 4)

__device__ __forceinline__ float dot4(float4 a, float4 b, float c) {
    c = fmaf(a.x, b.x, c); c = fmaf(a.y, b.y, c);
    c = fmaf(a.z, b.z, c); c = fmaf(a.w, b.w, c);
    return c;
}

__global__ __launch_bounds__(256, 2)
void flash_kernel(const float* __restrict__ u)
{
    extern __shared__ float sm[];
    float* Qs  = sm;                 // [64][QP]  (q + u_h)
    float* Ks  = Qs + 64*QP;         // [64][QP]
    float* Vs  = Ks + 64*QP;         // [64][64]
    float* Ps  = Vs + 64*64;         // [64][PP]
    float* red = Ps + 64*PP;         // [64][16]
    float* m_s = red + 64*16;        // [64]
    float* l_s = m_s + 64;           // [64]

    const int t  = threadIdx.x;
    const int tx = t & 15, ty = t >> 4;
    const int bh = blockIdx.y, b = bh >> 4, h = bh & 15;
    const int i0 = blockIdx.x << 6;

    const float* Qg = g_Q + (size_t)b*Sn*Dn + h*DHn;
    const float* Kg = g_K + (size_t)b*Sn*Dn + h*DHn;
    const float* Vg = g_V + (size_t)b*Sn*Dn + h*DHn;
    const float* Tg = g_T + (size_t)bh*Sn*Sn;

    // load Q tile (+u), natural [row][d] layout
    {
        const int lr = ty, ld = tx << 2;
        float4 u4 = *(const float4*)(u + h*DHn + ld);
#pragma unroll
        for (int it = 0; it < 4; it++) {
            int r = it*16 + lr;
            float4 q4 = *(const float4*)(Qg + (size_t)(i0 + r)*Dn + ld);
            Qs[r*QP + ld + 0] = q4.x + u4.x;
            Qs[r*QP + ld + 1] = q4.y + u4.y;
            Qs[r*QP + ld + 2] = q4.z + u4.z;
            Qs[r*QP + ld + 3] = q4.w + u4.w;
        }
    }
    if (t < 64) { m_s[t] = -1e30f; l_s[t] = 0.f; }
    float acc[4][4];
#pragma unroll
    for (int a = 0; a < 4; a++)
#pragma unroll
        for (int c = 0; c < 4; c++) acc[a][c] = 0.f;
    __syncthreads();

    for (int j0 = 0; j0 < Sn; j0 += 64) {
        // load K (natural [j][d]) and V tiles
        {
            const int lr = ty, ld = tx << 2;
#pragma unroll
            for (int it = 0; it < 4; it++) {
                int r = it*16 + lr;
                float4 k4 = *(const float4*)(Kg + (size_t)(j0 + r)*Dn + ld);
                Ks[r*QP + ld + 0] = k4.x; Ks[r*QP + ld + 1] = k4.y;
                Ks[r*QP + ld + 2] = k4.z; Ks[r*QP + ld + 3] = k4.w;
                float4 v4 = *(const float4*)(Vg + (size_t)(j0 + r)*Dn + ld);
                *(float4*)&Vs[(r << 6) + ld] = v4;
            }
        }
        __syncthreads();

        // ---- scores: rows i0+ty*4+a, cols j0+c*16+tx (strided -> conflict-free K loads)
        float s[4][4];
#pragma unroll
        for (int a = 0; a < 4; a++)
#pragma unroll
            for (int c = 0; c < 4; c++) s[a][c] = 0.f;

#pragma unroll 4
        for (int d = 0; d < 64; d += 4) {
            float4 q0 = *(const float4*)&Qs[(ty*4+0)*QP + d];
            float4 q1 = *(const float4*)&Qs[(ty*4+1)*QP + d];
            float4 q2 = *(const float4*)&Qs[(ty*4+2)*QP + d];
            float4 q3 = *(const float4*)&Qs[(ty*4+3)*QP + d];
            float4 k0 = *(const float4*)&Ks[(tx     )*QP + d];
            float4 k1 = *(const float4*)&Ks[(16 + tx)*QP + d];
            float4 k2 = *(const float4*)&Ks[(32 + tx)*QP + d];
            float4 k3 = *(const float4*)&Ks[(48 + tx)*QP + d];
            s[0][0]=dot4(q0,k0,s[0][0]); s[0][1]=dot4(q0,k1,s[0][1]);
            s[0][2]=dot4(q0,k2,s[0][2]); s[0][3]=dot4(q0,k3,s[0][3]);
            s[1][0]=dot4(q1,k0,s[1][0]); s[1][1]=dot4(q1,k1,s[1][1]);
            s[1][2]=dot4(q1,k2,s[1][2]); s[1][3]=dot4(q1,k3,s[1][3]);
            s[2][0]=dot4(q2,k0,s[2][0]); s[2][1]=dot4(q2,k1,s[2][1]);
            s[2][2]=dot4(q2,k2,s[2][2]); s[2][3]=dot4(q2,k3,s[2][3]);
            s[3][0]=dot4(q3,k0,s[3][0]); s[3][1]=dot4(q3,k1,s[3][1]);
            s[3][2]=dot4(q3,k2,s[3][2]); s[3][3]=dot4(q3,k3,s[3][3]);
        }

        // ---- add shifted BD from T, scale, local row max
        const float scale = 0.125f;
#pragma unroll
        for (int a = 0; a < 4; a++) {
            int i = i0 + ty*4 + a;
            float rm = -1e30f;
#pragma unroll
            for (int c = 0; c < 4; c++) {
                int j = j0 + c*16 + tx;
                float bd;
                if (j <= i)            bd = Tg[(size_t)i*Sn + (Sn - 1 - i + j)];
                else if (j == i + 1)   bd = 0.f;
                else                   bd = Tg[(size_t)(i + 1)*Sn + (j - i - 2)];
                float v = (s[a][c] + bd) * scale;
                s[a][c] = v;
                rm = fmaxf(rm, v);
            }
            red[(ty*4+a)*16 + tx] = rm;
        }
        __syncthreads();

        // ---- new running max + correction factor
        float mnew[4], f[4];
#pragma unroll
        for (int a = 0; a < 4; a++) {
            int r = ty*4 + a;
            float rm = red[r*16];
#pragma unroll
            for (int x2 = 1; x2 < 16; x2++) rm = fmaxf(rm, red[r*16 + x2]);
            float mo = m_s[r];
            mnew[a] = fmaxf(mo, rm);
            f[a] = __expf(mo - mnew[a]);
        }
        __syncthreads();   // all reads of red/m_s done before reuse

        // ---- p = exp(s - mnew), partial sums, rescale acc, stage P
#pragma unroll
        for (int a = 0; a < 4; a++) {
            int r = ty*4 + a;
            float ps = 0.f;
#pragma unroll
            for (int c = 0; c < 4; c++) {
                float p = __expf(s[a][c] - mnew[a]);
                Ps[r*PP + c*16 + tx] = p;
                ps += p;
            }
            red[r*16 + tx] = ps;
#pragma unroll
            for (int c = 0; c < 4; c++) acc[a][c] *= f[a];
        }
        __syncthreads();

        if (tx == 0) {
#pragma unroll
            for (int a = 0; a < 4; a++) {
                int r = ty*4 + a;
                float ls = l_s[r] * f[a];
#pragma unroll
                for (int x2 = 0; x2 < 16; x2++) ls += red[r*16 + x2];
                l_s[r] = ls;
                m_s[r] = mnew[a];
            }
        }

        // ---- acc += P @ V  (output cols = tx*4 + c)
#pragma unroll 8
        for (int j = 0; j < 64; j++) {
            float4 v4 = *(const float4*)&Vs[(j << 6) + (tx << 2)];
            float p0 = Ps[(ty*4+0)*PP + j];
            float p1 = Ps[(ty*4+1)*PP + j];
            float p2 = Ps[(ty*4+2)*PP + j];
            float p3 = Ps[(ty*4+3)*PP + j];
            acc[0][0]=fmaf(p0,v4.x,acc[0][0]); acc[0][1]=fmaf(p0,v4.y,acc[0][1]);
            acc[0][2]=fmaf(p0,v4.z,acc[0][2]); acc[0][3]=fmaf(p0,v4.w,acc[0][3]);
            acc[1][0]=fmaf(p1,v4.x,acc[1][0]); acc[1][1]=fmaf(p1,v4.y,acc[1][1]);
            acc[1][2]=fmaf(p1,v4.z,acc[1][2]); acc[1][3]=fmaf(p1,v4.w,acc[1][3]);
            acc[2][0]=fmaf(p2,v4.x,acc[2][0]); acc[2][1]=fmaf(p2,v4.y,acc[2][1]);
            acc[2][2]=fmaf(p2,v4.z,acc[2][2]); acc[2][3]=fmaf(p2,v4.w,acc[2][3]);
            acc[3][0]=fmaf(p3,v4.x,acc[3][0]); acc[3][1]=fmaf(p3,v4.y,acc[3][1]);
            acc[3][2]=fmaf(p3,v4.z,acc[3][2]); acc[3][3]=fmaf(p3,v4.w,acc[3][3]);
        }
        __syncthreads();
    }

    // ---- normalize and write out (layout [b, s, h*64+d] -> ready for @Wo)
#pragma unroll
    for (int a = 0; a < 4; a++) {
        int r = ty*4 + a;
        float inv = 1.f / l_s[r];
        float4 o = make_float4(acc[a][0]*inv, acc[a][1]*inv,
                               acc[a][2]*inv, acc[a][3]*inv);
        *(float4*)(g_AO + (size_t)b*Sn*Dn + (size_t)(i0 + r)*Dn + h*DHn + (tx << 2)) = o;
    }
}

// ---------------------------------------------------------------------------
// Launch
// ---------------------------------------------------------------------------
extern "C" void kernel_launch(void* const* d_in, const int* in_sizes, int n_in,
                              void* d_out, int out_size)
{
    const float* x   = (const float*)d_in[0];
    const float* pos = (const float*)d_in[1];
    const float* Wq  = (const float*)d_in[2];
    const float* bq  = (const float*)d_in[3];
    const float* Wk  = (const float*)d_in[4];
    const float* bk  = (const float*)d_in[5];
    const float* Wv  = (const float*)d_in[6];
    const float* bv  = (const float*)d_in[7];
    const float* Wo  = (const float*)d_in[8];
    const float* bo  = (const float*)d_in[9];
    const float* Wkr = (const float*)d_in[10];
    const float* bkr = (const float*)d_in[11];
    const float* u   = (const float*)d_in[12];
    // d_in[13] (v) intentionally unused: GH term is per-row constant -> softmax-invariant.

    float *pQ, *pK, *pV, *pKR, *pAO;
    cudaGetSymbolAddress((void**)&pQ,  g_Q);
    cudaGetSymbolAddress((void**)&pK,  g_K);
    cudaGetSymbolAddress((void**)&pV,  g_V);
    cudaGetSymbolAddress((void**)&pKR, g_KR);
    cudaGetSymbolAddress((void**)&pAO, g_AO);

    dim3 thr(256);
    // projections: Q, K, V from x ; KR from pos_emb
    gemm_nn_bias<<<dim3(Dn/128, (Bn*Sn)/128), thr>>>(x,   Wq,  bq,  pQ,  Bn*Sn, Dn, Dn);
    gemm_nn_bias<<<dim3(Dn/128, (Bn*Sn)/128), thr>>>(x,   Wk,  bk,  pK,  Bn*Sn, Dn, Dn);
    gemm_nn_bias<<<dim3(Dn/128, (Bn*Sn)/128), thr>>>(x,   Wv,  bv,  pV,  Bn*Sn, Dn, Dn);
    gemm_nn_bias<<<dim3(Dn/128,  Sn/128),     thr>>>(pos, Wkr, bkr, pKR, Sn,    Dn, Dn);
    // T = Q @ KR^T per (b,h)
    gemm_t_kernel<<<dim3(Sn/128, Sn/128, BHn), thr>>>();
    // fused attention
    cudaFuncSetAttribute(flash_kernel, cudaFuncAttributeMaxDynamicSharedMemorySize, FLASH_SMEM);
    flash_kernel<<<dim3(Sn/64, BHn), thr, FLASH_SMEM>>>(u);
    // output projection
    gemm_nn_bias<<<dim3(Dn/128, (Bn*Sn)/128), thr>>>(pAO, Wo, bo, (float*)d_out, Bn*Sn, Dn, Dn);
}

// round 3
// speedup vs baseline: 1.2152x; 1.2152x over previous
#include <cuda_runtime.h>
#include <cuda_bf16.h>
#include <math.h>
#include <stdint.h>

// Problem constants
#define Bn  2
#define Sn  2048
#define Dn  1024
#define Hn  16
#define DHn 64
#define BHn (Bn*Hn)

// ---------------------------------------------------------------------------
// Scratch (static __device__ — no runtime allocation, per harness rules)
// ---------------------------------------------------------------------------
__device__ float g_Q [(size_t)Bn*Sn*Dn];        // 16.8 MB
__device__ float g_K [(size_t)Bn*Sn*Dn];
__device__ float g_V [(size_t)Bn*Sn*Dn];
__device__ float g_KR[(size_t)Sn*Dn];           //  8.4 MB
__device__ float g_T [(size_t)BHn*Sn*Sn];       // 536 MB : T = Q @ KR^T per (b,h)
__device__ float g_AO[(size_t)Bn*Sn*Dn];        // attention output before Wo

// ---------------------------------------------------------------------------
// Warp-MMA helpers (sm_80-era PTX — valid on base sm_103 target)
// ---------------------------------------------------------------------------
__device__ __forceinline__ uint32_t smem_u32(const void* p) {
    uint32_t a;
    asm("{ .reg .u64 t; cvta.to.shared.u64 t, %1; cvt.u32.u64 %0, t; }"
        : "=r"(a) : "l"(p));
    return a;
}

__device__ __forceinline__ void ldm4(uint32_t addr, uint32_t* r) {
    asm volatile("ldmatrix.sync.aligned.m8n8.x4.shared.b16 {%0,%1,%2,%3}, [%4];"
        : "=r"(r[0]), "=r"(r[1]), "=r"(r[2]), "=r"(r[3]) : "r"(addr));
}

__device__ __forceinline__ void mma16816(float* c, const uint32_t* a, const uint32_t* b) {
    asm volatile(
        "mma.sync.aligned.m16n8k16.row.col.f32.bf16.bf16.f32 "
        "{%0,%1,%2,%3}, {%4,%5,%6,%7}, {%8,%9}, {%0,%1,%2,%3};"
        : "+f"(c[0]), "+f"(c[1]), "+f"(c[2]), "+f"(c[3])
        : "r"(a[0]), "r"(a[1]), "r"(a[2]), "r"(a[3]), "r"(b[0]), "r"(b[1]));
}

// fp32 -> (hi, lo) bf16x2 packing of two consecutive elements
__device__ __forceinline__ void cvt2(float x0, float x1, uint32_t& hi, uint32_t& lo) {
    __nv_bfloat16 h0 = __float2bfloat16(x0);
    __nv_bfloat16 h1 = __float2bfloat16(x1);
    __nv_bfloat16 l0 = __float2bfloat16(x0 - __bfloat162float(h0));
    __nv_bfloat16 l1 = __float2bfloat16(x1 - __bfloat162float(h1));
    hi = (uint32_t)__bfloat16_as_ushort(h0) | ((uint32_t)__bfloat16_as_ushort(h1) << 16);
    lo = (uint32_t)__bfloat16_as_ushort(l0) | ((uint32_t)__bfloat16_as_ushort(l1) << 16);
}

#define SPITCH 40   // smem row pitch in b16 (80B -> conflict-free ldmatrix rows)

// ---------------------------------------------------------------------------
// bf16x3 NN GEMM via mma.sync:  C[M,N] = A[M,K] @ W[K,N] + bias
// Block tile 128x128, K-chunk 32, 8 warps (warp tile 32x64).
// ---------------------------------------------------------------------------
__global__ __launch_bounds__(256, 1)
void mma_gemm_nn(const float* __restrict__ A, const float* __restrict__ W,
                 const float* __restrict__ bias, float* __restrict__ C,
                 int M, int N, int K)
{
    __shared__ __align__(16) uint16_t sAhi[128*SPITCH];
    __shared__ __align__(16) uint16_t sAlo[128*SPITCH];
    __shared__ __align__(16) uint16_t sBhi[128*SPITCH];
    __shared__ __align__(16) uint16_t sBlo[128*SPITCH];

    const int t = threadIdx.x, lane = t & 31, wid = t >> 5;
    const int row0 = blockIdx.y << 7, col0 = blockIdx.x << 7;
    const int m0w = (wid & 3) << 5;      // warp m offset (4 warps x 32 rows)
    const int n0w = (wid >> 2) << 6;     // warp n offset (2 warps x 64 cols)
    const int q = lane >> 3, r8 = lane & 7;

    // gmem load mapping
    const int ar = t >> 1, aks = (t & 1) << 4;      // A: 2 thr/row, 16 k each
    const int bn = t & 127, bks = (t >> 7) << 4;    // B: thread per n, 16 k each
    const float* Ag = A + (size_t)(row0 + ar) * K + aks;
    const float* Wg = W + (size_t)bks * N + col0 + bn;

    float ra[16], rb[16];
#pragma unroll
    for (int i = 0; i < 4; i++) *(float4*)(ra + 4*i) = *(const float4*)(Ag + 4*i);
#pragma unroll
    for (int i = 0; i < 16; i++) rb[i] = Wg[(size_t)i * N];

    float acc[2][8][4];
#pragma unroll
    for (int mt = 0; mt < 2; mt++)
#pragma unroll
        for (int nt = 0; nt < 8; nt++)
#pragma unroll
            for (int c = 0; c < 4; c++) acc[mt][nt][c] = 0.f;

    const uint32_t baseAhi = smem_u32(sAhi), baseAlo = smem_u32(sAlo);
    const uint32_t baseBhi = smem_u32(sBhi), baseBlo = smem_u32(sBlo);

    for (int k0 = 0; k0 < K; k0 += 32) {
        // stage prefetched chunk into smem (convert fp32 -> bf16 hi/lo)
#pragma unroll
        for (int i = 0; i < 16; i += 2) {
            uint32_t h, l;
            cvt2(ra[i], ra[i+1], h, l);
            *(uint32_t*)&sAhi[ar*SPITCH + aks + i] = h;
            *(uint32_t*)&sAlo[ar*SPITCH + aks + i] = l;
        }
#pragma unroll
        for (int i = 0; i < 16; i += 2) {
            uint32_t h, l;
            cvt2(rb[i], rb[i+1], h, l);
            *(uint32_t*)&sBhi[bn*SPITCH + bks + i] = h;
            *(uint32_t*)&sBlo[bn*SPITCH + bks + i] = l;
        }
        __syncthreads();

        // prefetch next chunk while MMAs run
        if (k0 + 32 < K) {
            const float* Ag2 = Ag + k0 + 32;
            const float* Wg2 = Wg + (size_t)(k0 + 32) * N;
#pragma unroll
            for (int i = 0; i < 4; i++) *(float4*)(ra + 4*i) = *(const float4*)(Ag2 + 4*i);
#pragma unroll
            for (int i = 0; i < 16; i++) rb[i] = Wg2[(size_t)i * N];
        }

#pragma unroll
        for (int ks = 0; ks < 2; ks++) {
            uint32_t ahi[2][4], alo[2][4];
#pragma unroll
            for (int mt = 0; mt < 2; mt++) {
                int row = m0w + mt*16 + r8 + (q & 1)*8;
                int col = ks*16 + (q >> 1)*8;
                uint32_t off = (uint32_t)(row*SPITCH + col) * 2;
                ldm4(baseAhi + off, ahi[mt]);
                ldm4(baseAlo + off, alo[mt]);
            }
            uint32_t bhi[8][2], blo[8][2];
#pragma unroll
            for (int bt = 0; bt < 4; bt++) {
                int row = n0w + bt*16 + r8 + (q >> 1)*8;
                int col = ks*16 + (q & 1)*8;
                uint32_t off = (uint32_t)(row*SPITCH + col) * 2;
                uint32_t tmp[4];
                ldm4(baseBhi + off, tmp);
                bhi[bt*2][0]=tmp[0]; bhi[bt*2][1]=tmp[1];
                bhi[bt*2+1][0]=tmp[2]; bhi[bt*2+1][1]=tmp[3];
                ldm4(baseBlo + off, tmp);
                blo[bt*2][0]=tmp[0]; blo[bt*2][1]=tmp[1];
                blo[bt*2+1][0]=tmp[2]; blo[bt*2+1][1]=tmp[3];
            }
#pragma unroll
            for (int mt = 0; mt < 2; mt++)
#pragma unroll
                for (int nt = 0; nt < 8; nt++) {
                    mma16816(acc[mt][nt], ahi[mt], bhi[nt]);
                    mma16816(acc[mt][nt], ahi[mt], blo[nt]);
                    mma16816(acc[mt][nt], alo[mt], bhi[nt]);
                }
        }
        __syncthreads();
    }

    // epilogue: c frag -> thread (m = base + lane/4 [, +8], n = base + (lane%4)*2)
#pragma unroll
    for (int mt = 0; mt < 2; mt++) {
        int m = row0 + m0w + mt*16 + lane/4;
#pragma unroll
        for (int nt = 0; nt < 8; nt++) {
            int n = col0 + n0w + nt*8 + (lane & 3)*2;
            float2 b2 = *(const float2*)(bias + n);
            float* Cp0 = C + (size_t)m * N + n;
            float* Cp1 = Cp0 + (size_t)8 * N;
            Cp0[0] = acc[mt][nt][0] + b2.x;  Cp0[1] = acc[mt][nt][1] + b2.y;
            Cp1[0] = acc[mt][nt][2] + b2.x;  Cp1[1] = acc[mt][nt][3] + b2.y;
        }
    }
}

// ---------------------------------------------------------------------------
// bf16x3 NT GEMM via mma.sync:  T[bh] = Q_bh [S,64] @ KR_h^T.  K=64.
// Both operands K-major (natural rows), so both load contiguously.
// ---------------------------------------------------------------------------
__global__ __launch_bounds__(256, 1)
void mma_gemm_t()
{
    __shared__ __align__(16) uint16_t sAhi[128*SPITCH];
    __shared__ __align__(16) uint16_t sAlo[128*SPITCH];
    __shared__ __align__(16) uint16_t sBhi[128*SPITCH];
    __shared__ __align__(16) uint16_t sBlo[128*SPITCH];

    const int t = threadIdx.x, lane = t & 31, wid = t >> 5;
    const int bh = blockIdx.z, b = bh >> 4, h = bh & 15;
    const int row0 = blockIdx.y << 7, col0 = blockIdx.x << 7;
    const int m0w = (wid & 3) << 5, n0w = (wid >> 2) << 6;
    const int q = lane >> 3, r8 = lane & 7;

    const float* Aq = g_Q  + (size_t)b * Sn * Dn + h * DHn;   // lda = Dn
    const float* Bm = g_KR + h * DHn;                         // ldb = Dn
    float* C = g_T + (size_t)bh * Sn * Sn;

    const int ar = t >> 1, aks = (t & 1) << 4;

    float acc[2][8][4];
#pragma unroll
    for (int mt = 0; mt < 2; mt++)
#pragma unroll
        for (int nt = 0; nt < 8; nt++)
#pragma unroll
            for (int c = 0; c < 4; c++) acc[mt][nt][c] = 0.f;

    const uint32_t baseAhi = smem_u32(sAhi), baseAlo = smem_u32(sAlo);
    const uint32_t baseBhi = smem_u32(sBhi), baseBlo = smem_u32(sBlo);

    for (int k0 = 0; k0 < DHn; k0 += 32) {
        const float* Ap = Aq + (size_t)(row0 + ar) * Dn + k0 + aks;
        const float* Bp = Bm + (size_t)(col0 + ar) * Dn + k0 + aks;
#pragma unroll
        for (int i = 0; i < 16; i += 4) {
            float4 va = *(const float4*)(Ap + i);
            uint32_t h0, l0, h1, l1;
            cvt2(va.x, va.y, h0, l0); cvt2(va.z, va.w, h1, l1);
            *(uint32_t*)&sAhi[ar*SPITCH + aks + i]     = h0;
            *(uint32_t*)&sAlo[ar*SPITCH + aks + i]     = l0;
            *(uint32_t*)&sAhi[ar*SPITCH + aks + i + 2] = h1;
            *(uint32_t*)&sAlo[ar*SPITCH + aks + i + 2] = l1;
            float4 vb = *(const float4*)(Bp + i);
            cvt2(vb.x, vb.y, h0, l0); cvt2(vb.z, vb.w, h1, l1);
            *(uint32_t*)&sBhi[ar*SPITCH + aks + i]     = h0;
            *(uint32_t*)&sBlo[ar*SPITCH + aks + i]     = l0;
            *(uint32_t*)&sBhi[ar*SPITCH + aks + i + 2] = h1;
            *(uint32_t*)&sBlo[ar*SPITCH + aks + i + 2] = l1;
        }
        __syncthreads();

#pragma unroll
        for (int ks = 0; ks < 2; ks++) {
            uint32_t ahi[2][4], alo[2][4];
#pragma unroll
            for (int mt = 0; mt < 2; mt++) {
                int row = m0w + mt*16 + r8 + (q & 1)*8;
                int col = ks*16 + (q >> 1)*8;
                uint32_t off = (uint32_t)(row*SPITCH + col) * 2;
                ldm4(baseAhi + off, ahi[mt]);
                ldm4(baseAlo + off, alo[mt]);
            }
            uint32_t bhi[8][2], blo[8][2];
#pragma unroll
            for (int bt = 0; bt < 4; bt++) {
                int row = n0w + bt*16 + r8 + (q >> 1)*8;
                int col = ks*16 + (q & 1)*8;
                uint32_t off = (uint32_t)(row*SPITCH + col) * 2;
                uint32_t tmp[4];
                ldm4(baseBhi + off, tmp);
                bhi[bt*2][0]=tmp[0]; bhi[bt*2][1]=tmp[1];
                bhi[bt*2+1][0]=tmp[2]; bhi[bt*2+1][1]=tmp[3];
                ldm4(baseBlo + off, tmp);
                blo[bt*2][0]=tmp[0]; blo[bt*2][1]=tmp[1];
                blo[bt*2+1][0]=tmp[2]; blo[bt*2+1][1]=tmp[3];
            }
#pragma unroll
            for (int mt = 0; mt < 2; mt++)
#pragma unroll
                for (int nt = 0; nt < 8; nt++) {
                    mma16816(acc[mt][nt], ahi[mt], bhi[nt]);
                    mma16816(acc[mt][nt], ahi[mt], blo[nt]);
                    mma16816(acc[mt][nt], alo[mt], bhi[nt]);
                }
        }
        __syncthreads();
    }

#pragma unroll
    for (int mt = 0; mt < 2; mt++) {
        int m = row0 + m0w + mt*16 + lane/4;
#pragma unroll
        for (int nt = 0; nt < 8; nt++) {
            int n = col0 + n0w + nt*8 + (lane & 3)*2;
            float* Cp0 = C + (size_t)m * Sn + n;
            float* Cp1 = Cp0 + (size_t)8 * Sn;
            Cp0[0] = acc[mt][nt][0];  Cp0[1] = acc[mt][nt][1];
            Cp1[0] = acc[mt][nt][2];  Cp1[1] = acc[mt][nt][3];
        }
    }
}

// ---------------------------------------------------------------------------
// Fused flash attention with relative-shift gather (unchanged from R1).
//   score(i,j) = ((q_i+u_h)·k_j + BD(i,j)) * 1/8,  softmax over j, @V
//   BD(i,j): j<=i -> T[i][S-1-i+j] ; j==i+1 -> 0 ; j>i+1 -> T[i+1][j-i-2]
// ---------------------------------------------------------------------------
#define QP 68
#define PP 65
#define FLASH_SMEM ((64*QP*2 + 64*64 + 64*PP + 64*16 + 128) * 4)

__device__ __forceinline__ float dot4(float4 a, float4 b, float c) {
    c = fmaf(a.x, b.x, c); c = fmaf(a.y, b.y, c);
    c = fmaf(a.z, b.z, c); c = fmaf(a.w, b.w, c);
    return c;
}

__global__ __launch_bounds__(256, 2)
void flash_kernel(const float* __restrict__ u)
{
    extern __shared__ float sm[];
    float* Qs  = sm;
    float* Ks  = Qs + 64*QP;
    float* Vs  = Ks + 64*QP;
    float* Ps  = Vs + 64*64;
    float* red = Ps + 64*PP;
    float* m_s = red + 64*16;
    float* l_s = m_s + 64;

    const int t  = threadIdx.x;
    const int tx = t & 15, ty = t >> 4;
    const int bh = blockIdx.y, b = bh >> 4, h = bh & 15;
    const int i0 = blockIdx.x << 6;

    const float* Qg = g_Q + (size_t)b*Sn*Dn + h*DHn;
    const float* Kg = g_K + (size_t)b*Sn*Dn + h*DHn;
    const float* Vg = g_V + (size_t)b*Sn*Dn + h*DHn;
    const float* Tg = g_T + (size_t)bh*Sn*Sn;

    {
        const int lr = ty, ld = tx << 2;
        float4 u4 = *(const float4*)(u + h*DHn + ld);
#pragma unroll
        for (int it = 0; it < 4; it++) {
            int r = it*16 + lr;
            float4 q4 = *(const float4*)(Qg + (size_t)(i0 + r)*Dn + ld);
            Qs[r*QP + ld + 0] = q4.x + u4.x;
            Qs[r*QP + ld + 1] = q4.y + u4.y;
            Qs[r*QP + ld + 2] = q4.z + u4.z;
            Qs[r*QP + ld + 3] = q4.w + u4.w;
        }
    }
    if (t < 64) { m_s[t] = -1e30f; l_s[t] = 0.f; }
    float acc[4][4];
#pragma unroll
    for (int a = 0; a < 4; a++)
#pragma unroll
        for (int c = 0; c < 4; c++) acc[a][c] = 0.f;
    __syncthreads();

    for (int j0 = 0; j0 < Sn; j0 += 64) {
        {
            const int lr = ty, ld = tx << 2;
#pragma unroll
            for (int it = 0; it < 4; it++) {
                int r = it*16 + lr;
                float4 k4 = *(const float4*)(Kg + (size_t)(j0 + r)*Dn + ld);
                Ks[r*QP + ld + 0] = k4.x; Ks[r*QP + ld + 1] = k4.y;
                Ks[r*QP + ld + 2] = k4.z; Ks[r*QP + ld + 3] = k4.w;
                float4 v4 = *(const float4*)(Vg + (size_t)(j0 + r)*Dn + ld);
                *(float4*)&Vs[(r << 6) + ld] = v4;
            }
        }
        __syncthreads();

        float s[4][4];
#pragma unroll
        for (int a = 0; a < 4; a++)
#pragma unroll
            for (int c = 0; c < 4; c++) s[a][c] = 0.f;

#pragma unroll 4
        for (int d = 0; d < 64; d += 4) {
            float4 q0 = *(const float4*)&Qs[(ty*4+0)*QP + d];
            float4 q1 = *(const float4*)&Qs[(ty*4+1)*QP + d];
            float4 q2 = *(const float4*)&Qs[(ty*4+2)*QP + d];
            float4 q3 = *(const float4*)&Qs[(ty*4+3)*QP + d];
            float4 k0 = *(const float4*)&Ks[(tx     )*QP + d];
            float4 k1 = *(const float4*)&Ks[(16 + tx)*QP + d];
            float4 k2 = *(const float4*)&Ks[(32 + tx)*QP + d];
            float4 k3 = *(const float4*)&Ks[(48 + tx)*QP + d];
            s[0][0]=dot4(q0,k0,s[0][0]); s[0][1]=dot4(q0,k1,s[0][1]);
            s[0][2]=dot4(q0,k2,s[0][2]); s[0][3]=dot4(q0,k3,s[0][3]);
            s[1][0]=dot4(q1,k0,s[1][0]); s[1][1]=dot4(q1,k1,s[1][1]);
            s[1][2]=dot4(q1,k2,s[1][2]); s[1][3]=dot4(q1,k3,s[1][3]);
            s[2][0]=dot4(q2,k0,s[2][0]); s[2][1]=dot4(q2,k1,s[2][1]);
            s[2][2]=dot4(q2,k2,s[2][2]); s[2][3]=dot4(q2,k3,s[2][3]);
            s[3][0]=dot4(q3,k0,s[3][0]); s[3][1]=dot4(q3,k1,s[3][1]);
            s[3][2]=dot4(q3,k2,s[3][2]); s[3][3]=dot4(q3,k3,s[3][3]);
        }

        const float scale = 0.125f;
#pragma unroll
        for (int a = 0; a < 4; a++) {
            int i = i0 + ty*4 + a;
            float rm = -1e30f;
#pragma unroll
            for (int c = 0; c < 4; c++) {
                int j = j0 + c*16 + tx;
                float bd;
                if (j <= i)            bd = Tg[(size_t)i*Sn + (Sn - 1 - i + j)];
                else if (j == i + 1)   bd = 0.f;
                else                   bd = Tg[(size_t)(i + 1)*Sn + (j - i - 2)];
                float v = (s[a][c] + bd) * scale;
                s[a][c] = v;
                rm = fmaxf(rm, v);
            }
            red[(ty*4+a)*16 + tx] = rm;
        }
        __syncthreads();

        float mnew[4], f[4];
#pragma unroll
        for (int a = 0; a < 4; a++) {
            int r = ty*4 + a;
            float rm = red[r*16];
#pragma unroll
            for (int x2 = 1; x2 < 16; x2++) rm = fmaxf(rm, red[r*16 + x2]);
            float mo = m_s[r];
            mnew[a] = fmaxf(mo, rm);
            f[a] = __expf(mo - mnew[a]);
        }
        __syncthreads();

#pragma unroll
        for (int a = 0; a < 4; a++) {
            int r = ty*4 + a;
            float ps = 0.f;
#pragma unroll
            for (int c = 0; c < 4; c++) {
                float p = __expf(s[a][c] - mnew[a]);
                Ps[r*PP + c*16 + tx] = p;
                ps += p;
            }
            red[r*16 + tx] = ps;
#pragma unroll
            for (int c = 0; c < 4; c++) acc[a][c] *= f[a];
        }
        __syncthreads();

        if (tx == 0) {
#pragma unroll
            for (int a = 0; a < 4; a++) {
                int r = ty*4 + a;
                float ls = l_s[r] * f[a];
#pragma unroll
                for (int x2 = 0; x2 < 16; x2++) ls += red[r*16 + x2];
                l_s[r] = ls;
                m_s[r] = mnew[a];
            }
        }

#pragma unroll 8
        for (int j = 0; j < 64; j++) {
            float4 v4 = *(const float4*)&Vs[(j << 6) + (tx << 2)];
            float p0 = Ps[(ty*4+0)*PP + j];
            float p1 = Ps[(ty*4+1)*PP + j];
            float p2 = Ps[(ty*4+2)*PP + j];
            float p3 = Ps[(ty*4+3)*PP + j];
            acc[0][0]=fmaf(p0,v4.x,acc[0][0]); acc[0][1]=fmaf(p0,v4.y,acc[0][1]);
            acc[0][2]=fmaf(p0,v4.z,acc[0][2]); acc[0][3]=fmaf(p0,v4.w,acc[0][3]);
            acc[1][0]=fmaf(p1,v4.x,acc[1][0]); acc[1][1]=fmaf(p1,v4.y,acc[1][1]);
            acc[1][2]=fmaf(p1,v4.z,acc[1][2]); acc[1][3]=fmaf(p1,v4.w,acc[1][3]);
            acc[2][0]=fmaf(p2,v4.x,acc[2][0]); acc[2][1]=fmaf(p2,v4.y,acc[2][1]);
            acc[2][2]=fmaf(p2,v4.z,acc[2][2]); acc[2][3]=fmaf(p2,v4.w,acc[2][3]);
            acc[3][0]=fmaf(p3,v4.x,acc[3][0]); acc[3][1]=fmaf(p3,v4.y,acc[3][1]);
            acc[3][2]=fmaf(p3,v4.z,acc[3][2]); acc[3][3]=fmaf(p3,v4.w,acc[3][3]);
        }
        __syncthreads();
    }

#pragma unroll
    for (int a = 0; a < 4; a++) {
        int r = ty*4 + a;
        float inv = 1.f / l_s[r];
        float4 o = make_float4(acc[a][0]*inv, acc[a][1]*inv,
                               acc[a][2]*inv, acc[a][3]*inv);
        *(float4*)(g_AO + (size_t)b*Sn*Dn + (size_t)(i0 + r)*Dn + h*DHn + (tx << 2)) = o;
    }
}

// ---------------------------------------------------------------------------
// Launch
// ---------------------------------------------------------------------------
extern "C" void kernel_launch(void* const* d_in, const int* in_sizes, int n_in,
                              void* d_out, int out_size)
{
    const float* x   = (const float*)d_in[0];
    const float* pos = (const float*)d_in[1];
    const float* Wq  = (const float*)d_in[2];
    const float* bq  = (const float*)d_in[3];
    const float* Wk  = (const float*)d_in[4];
    const float* bk  = (const float*)d_in[5];
    const float* Wv  = (const float*)d_in[6];
    const float* bv  = (const float*)d_in[7];
    const float* Wo  = (const float*)d_in[8];
    const float* bo  = (const float*)d_in[9];
    const float* Wkr = (const float*)d_in[10];
    const float* bkr = (const float*)d_in[11];
    const float* u   = (const float*)d_in[12];
    // d_in[13] (v) unused: GH term is per-row constant -> softmax-invariant.

    float *pQ, *pK, *pV, *pKR, *pAO;
    cudaGetSymbolAddress((void**)&pQ,  g_Q);
    cudaGetSymbolAddress((void**)&pK,  g_K);
    cudaGetSymbolAddress((void**)&pV,  g_V);
    cudaGetSymbolAddress((void**)&pKR, g_KR);
    cudaGetSymbolAddress((void**)&pAO, g_AO);

    cudaFuncSetAttribute(flash_kernel, cudaFuncAttributeMaxDynamicSharedMemorySize, FLASH_SMEM);

    dim3 thr(256);
    // projections (warp-MMA bf16x3)
    mma_gemm_nn<<<dim3(Dn/128, (Bn*Sn)/128), thr>>>(x,   Wq,  bq,  pQ,  Bn*Sn, Dn, Dn);
    mma_gemm_nn<<<dim3(Dn/128, (Bn*Sn)/128), thr>>>(x,   Wk,  bk,  pK,  Bn*Sn, Dn, Dn);
    mma_gemm_nn<<<dim3(Dn/128, (Bn*Sn)/128), thr>>>(x,   Wv,  bv,  pV,  Bn*Sn, Dn, Dn);
    mma_gemm_nn<<<dim3(Dn/128,  Sn/128),     thr>>>(pos, Wkr, bkr, pKR, Sn,    Dn, Dn);
    // T = Q @ KR^T per (b,h)
    mma_gemm_t<<<dim3(Sn/128, Sn/128, BHn), thr>>>();
    // fused attention (fp32)
    flash_kernel<<<dim3(Sn/64, BHn), thr, FLASH_SMEM>>>(u);
    // output projection
    mma_gemm_nn<<<dim3(Dn/128, (Bn*Sn)/128), thr>>>(pAO, Wo, bo, (float*)d_out, Bn*Sn, Dn, Dn);
}

// round 4
// speedup vs baseline: 1.9918x; 1.6391x over previous
#include <cuda_runtime.h>
#include <cuda_bf16.h>
#include <math.h>
#include <stdint.h>

// Problem constants
#define Bn  2
#define Sn  2048
#define Dn  1024
#define Hn  16
#define DHn 64
#define BHn (Bn*Hn)

// ---------------------------------------------------------------------------
// Scratch (static __device__ — no runtime allocation, per harness rules)
// ---------------------------------------------------------------------------
__device__ float g_Q [(size_t)Bn*Sn*Dn];
__device__ float g_K [(size_t)Bn*Sn*Dn];
__device__ float g_V [(size_t)Bn*Sn*Dn];
__device__ float g_KR[(size_t)Sn*Dn];
__device__ float g_T [(size_t)BHn*Sn*Sn];       // 536 MB : T = Q @ KR^T per (b,h)
__device__ float g_AO[(size_t)Bn*Sn*Dn];

// ---------------------------------------------------------------------------
// Warp-MMA helpers
// ---------------------------------------------------------------------------
__device__ __forceinline__ uint32_t smem_u32(const void* p) {
    uint32_t a;
    asm("{ .reg .u64 t; cvta.to.shared.u64 t, %1; cvt.u32.u64 %0, t; }"
        : "=r"(a) : "l"(p));
    return a;
}

__device__ __forceinline__ void ldm4(uint32_t addr, uint32_t* r) {
    asm volatile("ldmatrix.sync.aligned.m8n8.x4.shared.b16 {%0,%1,%2,%3}, [%4];"
        : "=r"(r[0]), "=r"(r[1]), "=r"(r[2]), "=r"(r[3]) : "r"(addr));
}

__device__ __forceinline__ void mma16816(float* c, const uint32_t* a, const uint32_t* b) {
    asm volatile(
        "mma.sync.aligned.m16n8k16.row.col.f32.bf16.bf16.f32 "
        "{%0,%1,%2,%3}, {%4,%5,%6,%7}, {%8,%9}, {%0,%1,%2,%3};"
        : "+f"(c[0]), "+f"(c[1]), "+f"(c[2]), "+f"(c[3])
        : "r"(a[0]), "r"(a[1]), "r"(a[2]), "r"(a[3]), "r"(b[0]), "r"(b[1]));
}

// fp32 -> (hi, lo) bf16x2 packing of two consecutive elements
__device__ __forceinline__ void cvt2(float x0, float x1, uint32_t& hi, uint32_t& lo) {
    __nv_bfloat16 h0 = __float2bfloat16(x0);
    __nv_bfloat16 h1 = __float2bfloat16(x1);
    __nv_bfloat16 l0 = __float2bfloat16(x0 - __bfloat162float(h0));
    __nv_bfloat16 l1 = __float2bfloat16(x1 - __bfloat162float(h1));
    hi = (uint32_t)__bfloat16_as_ushort(h0) | ((uint32_t)__bfloat16_as_ushort(h1) << 16);
    lo = (uint32_t)__bfloat16_as_ushort(l0) | ((uint32_t)__bfloat16_as_ushort(l1) << 16);
}

#define SPITCH 40   // GEMM smem pitch (b16)

// ---------------------------------------------------------------------------
// bf16x3 NN GEMM via mma.sync (unchanged from R3, passing)
// ---------------------------------------------------------------------------
__global__ __launch_bounds__(256, 1)
void mma_gemm_nn(const float* __restrict__ A, const float* __restrict__ W,
                 const float* __restrict__ bias, float* __restrict__ C,
                 int M, int N, int K)
{
    __shared__ __align__(16) uint16_t sAhi[128*SPITCH];
    __shared__ __align__(16) uint16_t sAlo[128*SPITCH];
    __shared__ __align__(16) uint16_t sBhi[128*SPITCH];
    __shared__ __align__(16) uint16_t sBlo[128*SPITCH];

    const int t = threadIdx.x, lane = t & 31, wid = t >> 5;
    const int row0 = blockIdx.y << 7, col0 = blockIdx.x << 7;
    const int m0w = (wid & 3) << 5;
    const int n0w = (wid >> 2) << 6;
    const int q = lane >> 3, r8 = lane & 7;

    const int ar = t >> 1, aks = (t & 1) << 4;
    const int bn = t & 127, bks = (t >> 7) << 4;
    const float* Ag = A + (size_t)(row0 + ar) * K + aks;
    const float* Wg = W + (size_t)bks * N + col0 + bn;

    float ra[16], rb[16];
#pragma unroll
    for (int i = 0; i < 4; i++) *(float4*)(ra + 4*i) = *(const float4*)(Ag + 4*i);
#pragma unroll
    for (int i = 0; i < 16; i++) rb[i] = Wg[(size_t)i * N];

    float acc[2][8][4];
#pragma unroll
    for (int mt = 0; mt < 2; mt++)
#pragma unroll
        for (int nt = 0; nt < 8; nt++)
#pragma unroll
            for (int c = 0; c < 4; c++) acc[mt][nt][c] = 0.f;

    const uint32_t baseAhi = smem_u32(sAhi), baseAlo = smem_u32(sAlo);
    const uint32_t baseBhi = smem_u32(sBhi), baseBlo = smem_u32(sBlo);

    for (int k0 = 0; k0 < K; k0 += 32) {
#pragma unroll
        for (int i = 0; i < 16; i += 2) {
            uint32_t h, l;
            cvt2(ra[i], ra[i+1], h, l);
            *(uint32_t*)&sAhi[ar*SPITCH + aks + i] = h;
            *(uint32_t*)&sAlo[ar*SPITCH + aks + i] = l;
        }
#pragma unroll
        for (int i = 0; i < 16; i += 2) {
            uint32_t h, l;
            cvt2(rb[i], rb[i+1], h, l);
            *(uint32_t*)&sBhi[bn*SPITCH + bks + i] = h;
            *(uint32_t*)&sBlo[bn*SPITCH + bks + i] = l;
        }
        __syncthreads();

        if (k0 + 32 < K) {
            const float* Ag2 = Ag + k0 + 32;
            const float* Wg2 = Wg + (size_t)(k0 + 32) * N;
#pragma unroll
            for (int i = 0; i < 4; i++) *(float4*)(ra + 4*i) = *(const float4*)(Ag2 + 4*i);
#pragma unroll
            for (int i = 0; i < 16; i++) rb[i] = Wg2[(size_t)i * N];
        }

#pragma unroll
        for (int ks = 0; ks < 2; ks++) {
            uint32_t ahi[2][4], alo[2][4];
#pragma unroll
            for (int mt = 0; mt < 2; mt++) {
                int row = m0w + mt*16 + r8 + (q & 1)*8;
                int col = ks*16 + (q >> 1)*8;
                uint32_t off = (uint32_t)(row*SPITCH + col) * 2;
                ldm4(baseAhi + off, ahi[mt]);
                ldm4(baseAlo + off, alo[mt]);
            }
            uint32_t bhi[8][2], blo[8][2];
#pragma unroll
            for (int bt = 0; bt < 4; bt++) {
                int row = n0w + bt*16 + r8 + (q >> 1)*8;
                int col = ks*16 + (q & 1)*8;
                uint32_t off = (uint32_t)(row*SPITCH + col) * 2;
                uint32_t tmp[4];
                ldm4(baseBhi + off, tmp);
                bhi[bt*2][0]=tmp[0]; bhi[bt*2][1]=tmp[1];
                bhi[bt*2+1][0]=tmp[2]; bhi[bt*2+1][1]=tmp[3];
                ldm4(baseBlo + off, tmp);
                blo[bt*2][0]=tmp[0]; blo[bt*2][1]=tmp[1];
                blo[bt*2+1][0]=tmp[2]; blo[bt*2+1][1]=tmp[3];
            }
#pragma unroll
            for (int mt = 0; mt < 2; mt++)
#pragma unroll
                for (int nt = 0; nt < 8; nt++) {
                    mma16816(acc[mt][nt], ahi[mt], bhi[nt]);
                    mma16816(acc[mt][nt], ahi[mt], blo[nt]);
                    mma16816(acc[mt][nt], alo[mt], bhi[nt]);
                }
        }
        __syncthreads();
    }

#pragma unroll
    for (int mt = 0; mt < 2; mt++) {
        int m = row0 + m0w + mt*16 + lane/4;
#pragma unroll
        for (int nt = 0; nt < 8; nt++) {
            int n = col0 + n0w + nt*8 + (lane & 3)*2;
            float2 b2 = *(const float2*)(bias + n);
            float* Cp0 = C + (size_t)m * N + n;
            float* Cp1 = Cp0 + (size_t)8 * N;
            Cp0[0] = acc[mt][nt][0] + b2.x;  Cp0[1] = acc[mt][nt][1] + b2.y;
            Cp1[0] = acc[mt][nt][2] + b2.x;  Cp1[1] = acc[mt][nt][3] + b2.y;
        }
    }
}

// ---------------------------------------------------------------------------
// bf16x3 NT GEMM:  T[bh] = Q_bh [S,64] @ KR_h^T  (unchanged from R3)
// ---------------------------------------------------------------------------
__global__ __launch_bounds__(256, 1)
void mma_gemm_t()
{
    __shared__ __align__(16) uint16_t sAhi[128*SPITCH];
    __shared__ __align__(16) uint16_t sAlo[128*SPITCH];
    __shared__ __align__(16) uint16_t sBhi[128*SPITCH];
    __shared__ __align__(16) uint16_t sBlo[128*SPITCH];

    const int t = threadIdx.x, lane = t & 31, wid = t >> 5;
    const int bh = blockIdx.z, b = bh >> 4, h = bh & 15;
    const int row0 = blockIdx.y << 7, col0 = blockIdx.x << 7;
    const int m0w = (wid & 3) << 5, n0w = (wid >> 2) << 6;
    const int q = lane >> 3, r8 = lane & 7;

    const float* Aq = g_Q  + (size_t)b * Sn * Dn + h * DHn;
    const float* Bm = g_KR + h * DHn;
    float* C = g_T + (size_t)bh * Sn * Sn;

    const int ar = t >> 1, aks = (t & 1) << 4;

    float acc[2][8][4];
#pragma unroll
    for (int mt = 0; mt < 2; mt++)
#pragma unroll
        for (int nt = 0; nt < 8; nt++)
#pragma unroll
            for (int c = 0; c < 4; c++) acc[mt][nt][c] = 0.f;

    const uint32_t baseAhi = smem_u32(sAhi), baseAlo = smem_u32(sAlo);
    const uint32_t baseBhi = smem_u32(sBhi), baseBlo = smem_u32(sBlo);

    for (int k0 = 0; k0 < DHn; k0 += 32) {
        const float* Ap = Aq + (size_t)(row0 + ar) * Dn + k0 + aks;
        const float* Bp = Bm + (size_t)(col0 + ar) * Dn + k0 + aks;
#pragma unroll
        for (int i = 0; i < 16; i += 4) {
            float4 va = *(const float4*)(Ap + i);
            uint32_t h0, l0, h1, l1;
            cvt2(va.x, va.y, h0, l0); cvt2(va.z, va.w, h1, l1);
            *(uint32_t*)&sAhi[ar*SPITCH + aks + i]     = h0;
            *(uint32_t*)&sAlo[ar*SPITCH + aks + i]     = l0;
            *(uint32_t*)&sAhi[ar*SPITCH + aks + i + 2] = h1;
            *(uint32_t*)&sAlo[ar*SPITCH + aks + i + 2] = l1;
            float4 vb = *(const float4*)(Bp + i);
            cvt2(vb.x, vb.y, h0, l0); cvt2(vb.z, vb.w, h1, l1);
            *(uint32_t*)&sBhi[ar*SPITCH + aks + i]     = h0;
            *(uint32_t*)&sBlo[ar*SPITCH + aks + i]     = l0;
            *(uint32_t*)&sBhi[ar*SPITCH + aks + i + 2] = h1;
            *(uint32_t*)&sBlo[ar*SPITCH + aks + i + 2] = l1;
        }
        __syncthreads();

#pragma unroll
        for (int ks = 0; ks < 2; ks++) {
            uint32_t ahi[2][4], alo[2][4];
#pragma unroll
            for (int mt = 0; mt < 2; mt++) {
                int row = m0w + mt*16 + r8 + (q & 1)*8;
                int col = ks*16 + (q >> 1)*8;
                uint32_t off = (uint32_t)(row*SPITCH + col) * 2;
                ldm4(baseAhi + off, ahi[mt]);
                ldm4(baseAlo + off, alo[mt]);
            }
            uint32_t bhi[8][2], blo[8][2];
#pragma unroll
            for (int bt = 0; bt < 4; bt++) {
                int row = n0w + bt*16 + r8 + (q >> 1)*8;
                int col = ks*16 + (q & 1)*8;
                uint32_t off = (uint32_t)(row*SPITCH + col) * 2;
                uint32_t tmp[4];
                ldm4(baseBhi + off, tmp);
                bhi[bt*2][0]=tmp[0]; bhi[bt*2][1]=tmp[1];
                bhi[bt*2+1][0]=tmp[2]; bhi[bt*2+1][1]=tmp[3];
                ldm4(baseBlo + off, tmp);
                blo[bt*2][0]=tmp[0]; blo[bt*2][1]=tmp[1];
                blo[bt*2+1][0]=tmp[2]; blo[bt*2+1][1]=tmp[3];
            }
#pragma unroll
            for (int mt = 0; mt < 2; mt++)
#pragma unroll
                for (int nt = 0; nt < 8; nt++) {
                    mma16816(acc[mt][nt], ahi[mt], bhi[nt]);
                    mma16816(acc[mt][nt], ahi[mt], blo[nt]);
                    mma16816(acc[mt][nt], alo[mt], bhi[nt]);
                }
        }
        __syncthreads();
    }

#pragma unroll
    for (int mt = 0; mt < 2; mt++) {
        int m = row0 + m0w + mt*16 + lane/4;
#pragma unroll
        for (int nt = 0; nt < 8; nt++) {
            int n = col0 + n0w + nt*8 + (lane & 3)*2;
            float* Cp0 = C + (size_t)m * Sn + n;
            float* Cp1 = Cp0 + (size_t)8 * Sn;
            Cp0[0] = acc[mt][nt][0];  Cp0[1] = acc[mt][nt][1];
            Cp1[0] = acc[mt][nt][2];  Cp1[1] = acc[mt][nt][3];
        }
    }
}

// ---------------------------------------------------------------------------
// Flash attention on tensor cores (bf16x3), relative-shift gather from g_T.
// Block: 128 q-rows x one bh. 8 warps, each owns 16 q-rows. K/V tiles of 64.
//   s(i,j) = (q_i+u_h)·k_j*0.125 + BD(i,j)*0.125 ; online softmax ; @V
//   BD(i,j): j<=i -> T[i][S-1-i+j] ; j==i+1 -> 0 ; j>i+1 -> T[i+1][j-i-2]
// ---------------------------------------------------------------------------
#define FP 72   // flash smem pitch (b16); 144B rows -> conflict-free ldmatrix
// dynamic smem layout (b16 offsets)
#define FQHI 0
#define FQLO (128*FP)
#define FKHI (2*128*FP)
#define FKLO (2*128*FP + 64*FP)
#define FVHI (2*128*FP + 2*64*FP)
#define FVLO (2*128*FP + 3*64*FP)
#define FLASH_SMEM ((2*128*FP + 4*64*FP) * 2)

__global__ __launch_bounds__(256, 1)
void flash_mma(const float* __restrict__ u)
{
    extern __shared__ __align__(16) uint16_t fsm[];
    const int t = threadIdx.x, lane = t & 31, w = t >> 5;
    const int q = lane >> 3, r8 = lane & 7;
    const int r = lane >> 2, qq = lane & 3;
    const int bh = blockIdx.y, b = bh >> 4, h = bh & 15;
    const int i0 = blockIdx.x << 7;

    const float* Qg = g_Q + ((size_t)b*Sn + i0)*Dn + h*DHn;
    const float* Kg = g_K + (size_t)b*Sn*Dn + h*DHn;
    const float* Vg = g_V + (size_t)b*Sn*Dn + h*DHn;
    const float* Tg = g_T + (size_t)bh*Sn*Sn;

    const uint32_t base = smem_u32(fsm);

    // ---- stage Q: (q + u)*0.125 -> hi/lo bf16, rows [0,128)
    {
        const int qr = t >> 1, cb = (t & 1) << 5;
        const float* Qp = Qg + (size_t)qr * Dn + cb;
        const float* up = u + h*DHn + cb;
#pragma unroll
        for (int i = 0; i < 32; i += 4) {
            float4 v = *(const float4*)(Qp + i);
            float4 uv = *(const float4*)(up + i);
            uint32_t h0, l0, h1, l1;
            cvt2((v.x+uv.x)*0.125f, (v.y+uv.y)*0.125f, h0, l0);
            cvt2((v.z+uv.z)*0.125f, (v.w+uv.w)*0.125f, h1, l1);
            *(uint32_t*)&fsm[FQHI + qr*FP + cb + i]     = h0;
            *(uint32_t*)&fsm[FQLO + qr*FP + cb + i]     = l0;
            *(uint32_t*)&fsm[FQHI + qr*FP + cb + i + 2] = h1;
            *(uint32_t*)&fsm[FQLO + qr*FP + cb + i + 2] = l1;
        }
    }
    __syncthreads();

    // ---- Q fragments, register-resident for the whole kernel
    uint32_t qhi[4][4], qlo[4][4];
#pragma unroll
    for (int ks = 0; ks < 4; ks++) {
        int row = w*16 + r8 + (q & 1)*8;
        int col = ks*16 + (q >> 1)*8;
        uint32_t off = (uint32_t)(row*FP + col) * 2;
        ldm4(base + (FQHI*2) + off, qhi[ks]);
        ldm4(base + (FQLO*2) + off, qlo[ks]);
    }

    float pacc[8][4];
#pragma unroll
    for (int dt = 0; dt < 8; dt++)
#pragma unroll
        for (int c = 0; c < 4; c++) pacc[dt][c] = 0.f;
    float m0 = -1e30f, m1 = -1e30f, l0 = 0.f, l1 = 0.f;

    const int i_r  = i0 + w*16 + r;     // this thread's two rows
    const int i_r8 = i_r + 8;

    for (int j0 = 0; j0 < Sn; j0 += 64) {
        // ---- load K tile [j][d] and V tile transposed [d][j], hi/lo
        {
            const int jr = t >> 2, cb = (t & 3) << 4;
            const float* Kp = Kg + (size_t)(j0 + jr) * Dn + cb;
            const float* Vp = Vg + (size_t)(j0 + jr) * Dn + cb;
#pragma unroll
            for (int i = 0; i < 16; i += 4) {
                float4 kv = *(const float4*)(Kp + i);
                uint32_t h0, l0_, h1, l1_;
                cvt2(kv.x, kv.y, h0, l0_); cvt2(kv.z, kv.w, h1, l1_);
                *(uint32_t*)&fsm[FKHI + jr*FP + cb + i]     = h0;
                *(uint32_t*)&fsm[FKLO + jr*FP + cb + i]     = l0_;
                *(uint32_t*)&fsm[FKHI + jr*FP + cb + i + 2] = h1;
                *(uint32_t*)&fsm[FKLO + jr*FP + cb + i + 2] = l1_;
                float4 vv = *(const float4*)(Vp + i);
                float vals[4] = {vv.x, vv.y, vv.z, vv.w};
#pragma unroll
                for (int e = 0; e < 4; e++) {
                    __nv_bfloat16 hb = __float2bfloat16(vals[e]);
                    __nv_bfloat16 lb = __float2bfloat16(vals[e] - __bfloat162float(hb));
                    fsm[FVHI + (cb + i + e)*FP + jr] = __bfloat16_as_ushort(hb);
                    fsm[FVLO + (cb + i + e)*FP + jr] = __bfloat16_as_ushort(lb);
                }
            }
        }
        __syncthreads();

        // ---- S = Qs @ K^T  (bf16x3)
        float sacc[8][4];
#pragma unroll
        for (int nt = 0; nt < 8; nt++)
#pragma unroll
            for (int c = 0; c < 4; c++) sacc[nt][c] = 0.f;

#pragma unroll
        for (int ks = 0; ks < 4; ks++) {
            uint32_t kh[8][2], kl[8][2];
#pragma unroll
            for (int bt = 0; bt < 4; bt++) {
                int row = bt*16 + r8 + (q >> 1)*8;
                int col = ks*16 + (q & 1)*8;
                uint32_t off = (uint32_t)(row*FP + col) * 2;
                uint32_t tmp[4];
                ldm4(base + (FKHI*2) + off, tmp);
                kh[bt*2][0]=tmp[0]; kh[bt*2][1]=tmp[1];
                kh[bt*2+1][0]=tmp[2]; kh[bt*2+1][1]=tmp[3];
                ldm4(base + (FKLO*2) + off, tmp);
                kl[bt*2][0]=tmp[0]; kl[bt*2][1]=tmp[1];
                kl[bt*2+1][0]=tmp[2]; kl[bt*2+1][1]=tmp[3];
            }
#pragma unroll
            for (int nt = 0; nt < 8; nt++) {
                mma16816(sacc[nt], qhi[ks], kh[nt]);
                mma16816(sacc[nt], qhi[ks], kl[nt]);
                mma16816(sacc[nt], qlo[ks], kh[nt]);
            }
        }

        // ---- add BD*0.125 from T, row max
        float ml0 = -1e30f, ml1 = -1e30f;
#pragma unroll
        for (int nt = 0; nt < 8; nt++) {
            int jb = j0 + nt*8 + 2*qq;
#pragma unroll
            for (int e = 0; e < 4; e++) {
                int i = (e < 2) ? i_r : i_r8;
                int j = jb + (e & 1);
                int ir = (j <= i) ? i : i + 1;
                int ic = (j <= i) ? (Sn - 1 - i + j) : (j - i - 2);
                float bd = __ldg(Tg + (size_t)ir * Sn + ic);
                bd = (j == i + 1) ? 0.f : bd;
                float sv = fmaf(bd, 0.125f, sacc[nt][e]);
                sacc[nt][e] = sv;
                if (e < 2) ml0 = fmaxf(ml0, sv); else ml1 = fmaxf(ml1, sv);
            }
        }
        ml0 = fmaxf(ml0, __shfl_xor_sync(0xFFFFFFFFu, ml0, 1));
        ml0 = fmaxf(ml0, __shfl_xor_sync(0xFFFFFFFFu, ml0, 2));
        ml1 = fmaxf(ml1, __shfl_xor_sync(0xFFFFFFFFu, ml1, 1));
        ml1 = fmaxf(ml1, __shfl_xor_sync(0xFFFFFFFFu, ml1, 2));

        float mn0 = fmaxf(m0, ml0), mn1 = fmaxf(m1, ml1);
        float f0 = __expf(m0 - mn0), f1 = __expf(m1 - mn1);
        m0 = mn0; m1 = mn1;

        // ---- P = exp(s - m), row sums
        float ls0 = 0.f, ls1 = 0.f;
#pragma unroll
        for (int nt = 0; nt < 8; nt++) {
            float p0 = __expf(sacc[nt][0] - m0);
            float p1 = __expf(sacc[nt][1] - m0);
            float p2 = __expf(sacc[nt][2] - m1);
            float p3 = __expf(sacc[nt][3] - m1);
            sacc[nt][0] = p0; sacc[nt][1] = p1; sacc[nt][2] = p2; sacc[nt][3] = p3;
            ls0 += p0 + p1;  ls1 += p2 + p3;
        }
        ls0 += __shfl_xor_sync(0xFFFFFFFFu, ls0, 1);
        ls0 += __shfl_xor_sync(0xFFFFFFFFu, ls0, 2);
        ls1 += __shfl_xor_sync(0xFFFFFFFFu, ls1, 1);
        ls1 += __shfl_xor_sync(0xFFFFFFFFu, ls1, 2);
        l0 = l0 * f0 + ls0;
        l1 = l1 * f1 + ls1;

        // ---- rescale output accumulators
#pragma unroll
        for (int dt = 0; dt < 8; dt++) {
            pacc[dt][0] *= f0; pacc[dt][1] *= f0;
            pacc[dt][2] *= f1; pacc[dt][3] *= f1;
        }

        // ---- pack P into A-fragments (C frag pair -> A frag layout match)
        uint32_t phi[4][4], plo[4][4];
#pragma unroll
        for (int ks = 0; ks < 4; ks++) {
            cvt2(sacc[2*ks][0],   sacc[2*ks][1],   phi[ks][0], plo[ks][0]);
            cvt2(sacc[2*ks][2],   sacc[2*ks][3],   phi[ks][1], plo[ks][1]);
            cvt2(sacc[2*ks+1][0], sacc[2*ks+1][1], phi[ks][2], plo[ks][2]);
            cvt2(sacc[2*ks+1][2], sacc[2*ks+1][3], phi[ks][3], plo[ks][3]);
        }

        // ---- pacc += P @ V  (bf16x3), B frags from transposed V [d][j]
#pragma unroll
        for (int ks = 0; ks < 4; ks++) {
            uint32_t vh[8][2], vl[8][2];
#pragma unroll
            for (int bt = 0; bt < 4; bt++) {
                int row = bt*16 + r8 + (q >> 1)*8;   // d
                int col = ks*16 + (q & 1)*8;         // j
                uint32_t off = (uint32_t)(row*FP + col) * 2;
                uint32_t tmp[4];
                ldm4(base + (FVHI*2) + off, tmp);
                vh[bt*2][0]=tmp[0]; vh[bt*2][1]=tmp[1];
                vh[bt*2+1][0]=tmp[2]; vh[bt*2+1][1]=tmp[3];
                ldm4(base + (FVLO*2) + off, tmp);
                vl[bt*2][0]=tmp[0]; vl[bt*2][1]=tmp[1];
                vl[bt*2+1][0]=tmp[2]; vl[bt*2+1][1]=tmp[3];
            }
#pragma unroll
            for (int dt = 0; dt < 8; dt++) {
                mma16816(pacc[dt], phi[ks], vh[dt]);
                mma16816(pacc[dt], phi[ks], vl[dt]);
                mma16816(pacc[dt], plo[ks], vh[dt]);
            }
        }
        __syncthreads();
    }

    // ---- normalize & write out: g_AO[b][i][h*64 + d]
    float inv0 = 1.f / l0, inv1 = 1.f / l1;
    float* Og = g_AO + (size_t)b*Sn*Dn + h*DHn;
#pragma unroll
    for (int dt = 0; dt < 8; dt++) {
        int d = dt*8 + 2*qq;
        float2 o0 = make_float2(pacc[dt][0]*inv0, pacc[dt][1]*inv0);
        float2 o1 = make_float2(pacc[dt][2]*inv1, pacc[dt][3]*inv1);
        *(float2*)(Og + (size_t)i_r  * Dn + d) = o0;
        *(float2*)(Og + (size_t)i_r8 * Dn + d) = o1;
    }
}

// ---------------------------------------------------------------------------
// Launch
// ---------------------------------------------------------------------------
extern "C" void kernel_launch(void* const* d_in, const int* in_sizes, int n_in,
                              void* d_out, int out_size)
{
    const float* x   = (const float*)d_in[0];
    const float* pos = (const float*)d_in[1];
    const float* Wq  = (const float*)d_in[2];
    const float* bq  = (const float*)d_in[3];
    const float* Wk  = (const float*)d_in[4];
    const float* bk  = (const float*)d_in[5];
    const float* Wv  = (const float*)d_in[6];
    const float* bv  = (const float*)d_in[7];
    const float* Wo  = (const float*)d_in[8];
    const float* bo  = (const float*)d_in[9];
    const float* Wkr = (const float*)d_in[10];
    const float* bkr = (const float*)d_in[11];
    const float* u   = (const float*)d_in[12];
    // d_in[13] (v) unused: GH term is per-row constant -> softmax-invariant.

    float *pQ, *pK, *pV, *pKR, *pAO;
    cudaGetSymbolAddress((void**)&pQ,  g_Q);
    cudaGetSymbolAddress((void**)&pK,  g_K);
    cudaGetSymbolAddress((void**)&pV,  g_V);
    cudaGetSymbolAddress((void**)&pKR, g_KR);
    cudaGetSymbolAddress((void**)&pAO, g_AO);

    cudaFuncSetAttribute(flash_mma, cudaFuncAttributeMaxDynamicSharedMemorySize, FLASH_SMEM);

    dim3 thr(256);
    mma_gemm_nn<<<dim3(Dn/128, (Bn*Sn)/128), thr>>>(x,   Wq,  bq,  pQ,  Bn*Sn, Dn, Dn);
    mma_gemm_nn<<<dim3(Dn/128, (Bn*Sn)/128), thr>>>(x,   Wk,  bk,  pK,  Bn*Sn, Dn, Dn);
    mma_gemm_nn<<<dim3(Dn/128, (Bn*Sn)/128), thr>>>(x,   Wv,  bv,  pV,  Bn*Sn, Dn, Dn);
    mma_gemm_nn<<<dim3(Dn/128,  Sn/128),     thr>>>(pos, Wkr, bkr, pKR, Sn,    Dn, Dn);
    mma_gemm_t<<<dim3(Sn/128, Sn/128, BHn), thr>>>();
    flash_mma<<<dim3(Sn/128, BHn), thr, FLASH_SMEM>>>(u);
    mma_gemm_nn<<<dim3(Dn/128, (Bn*Sn)/128), thr>>>(pAO, Wo, bo, (float*)d_out, Bn*Sn, Dn, Dn);
}

// round 5
// speedup vs baseline: 2.1125x; 1.0606x over previous
#include <cuda_runtime.h>
#include <cuda_bf16.h>
#include <math.h>
#include <stdint.h>

// Problem constants
#define Bn  2
#define Sn  2048
#define Dn  1024
#define Hn  16
#define DHn 64
#define BHn (Bn*Hn)

// ---------------------------------------------------------------------------
// Scratch (static __device__ — no runtime allocation)
// ---------------------------------------------------------------------------
__device__ float g_Q [(size_t)Bn*Sn*Dn];
__device__ float g_K [(size_t)Bn*Sn*Dn];
__device__ float g_V [(size_t)Bn*Sn*Dn];
__device__ float g_KR[(size_t)Sn*Dn];
__device__ float g_T [(size_t)BHn*Sn*Sn];       // 536 MB : T = Q @ KR^T per (b,h)
__device__ float g_AO[(size_t)Bn*Sn*Dn];

// ---------------------------------------------------------------------------
// Warp-MMA helpers
// ---------------------------------------------------------------------------
__device__ __forceinline__ uint32_t smem_u32(const void* p) {
    uint32_t a;
    asm("{ .reg .u64 t; cvta.to.shared.u64 t, %1; cvt.u32.u64 %0, t; }"
        : "=r"(a) : "l"(p));
    return a;
}

__device__ __forceinline__ void ldm4(uint32_t addr, uint32_t* r) {
    asm volatile("ldmatrix.sync.aligned.m8n8.x4.shared.b16 {%0,%1,%2,%3}, [%4];"
        : "=r"(r[0]), "=r"(r[1]), "=r"(r[2]), "=r"(r[3]) : "r"(addr));
}

__device__ __forceinline__ void ldm4t(uint32_t addr, uint32_t* r) {
    asm volatile("ldmatrix.sync.aligned.m8n8.x4.trans.shared.b16 {%0,%1,%2,%3}, [%4];"
        : "=r"(r[0]), "=r"(r[1]), "=r"(r[2]), "=r"(r[3]) : "r"(addr));
}

__device__ __forceinline__ void mma16816(float* c, const uint32_t* a, const uint32_t* b) {
    asm volatile(
        "mma.sync.aligned.m16n8k16.row.col.f32.bf16.bf16.f32 "
        "{%0,%1,%2,%3}, {%4,%5,%6,%7}, {%8,%9}, {%0,%1,%2,%3};"
        : "+f"(c[0]), "+f"(c[1]), "+f"(c[2]), "+f"(c[3])
        : "r"(a[0]), "r"(a[1]), "r"(a[2]), "r"(a[3]), "r"(b[0]), "r"(b[1]));
}

__device__ __forceinline__ void cvt2(float x0, float x1, uint32_t& hi, uint32_t& lo) {
    __nv_bfloat16 h0 = __float2bfloat16(x0);
    __nv_bfloat16 h1 = __float2bfloat16(x1);
    __nv_bfloat16 l0 = __float2bfloat16(x0 - __bfloat162float(h0));
    __nv_bfloat16 l1 = __float2bfloat16(x1 - __bfloat162float(h1));
    hi = (uint32_t)__bfloat16_as_ushort(h0) | ((uint32_t)__bfloat16_as_ushort(h1) << 16);
    lo = (uint32_t)__bfloat16_as_ushort(l0) | ((uint32_t)__bfloat16_as_ushort(l1) << 16);
}

#define SPITCH 40

// ---------------------------------------------------------------------------
// bf16x3 NN GEMM body (shared by fused-projection kernel and Wo kernel)
// ---------------------------------------------------------------------------
__device__ __forceinline__
void gemm_body(const float* __restrict__ A, const float* __restrict__ W,
               const float* __restrict__ bias, float* __restrict__ C,
               int N, int K, int row0, int col0)
{
    __shared__ __align__(16) uint16_t sAhi[128*SPITCH];
    __shared__ __align__(16) uint16_t sAlo[128*SPITCH];
    __shared__ __align__(16) uint16_t sBhi[128*SPITCH];
    __shared__ __align__(16) uint16_t sBlo[128*SPITCH];

    const int t = threadIdx.x, lane = t & 31, wid = t >> 5;
    const int m0w = (wid & 3) << 5;
    const int n0w = (wid >> 2) << 6;
    const int q = lane >> 3, r8 = lane & 7;

    const int ar = t >> 1, aks = (t & 1) << 4;
    const int bn = t & 127, bks = (t >> 7) << 4;
    const float* Ag = A + (size_t)(row0 + ar) * K + aks;
    const float* Wg = W + (size_t)bks * N + col0 + bn;

    float ra[16], rb[16];
#pragma unroll
    for (int i = 0; i < 4; i++) *(float4*)(ra + 4*i) = *(const float4*)(Ag + 4*i);
#pragma unroll
    for (int i = 0; i < 16; i++) rb[i] = Wg[(size_t)i * N];

    float acc[2][8][4];
#pragma unroll
    for (int mt = 0; mt < 2; mt++)
#pragma unroll
        for (int nt = 0; nt < 8; nt++)
#pragma unroll
            for (int c = 0; c < 4; c++) acc[mt][nt][c] = 0.f;

    const uint32_t baseAhi = smem_u32(sAhi), baseAlo = smem_u32(sAlo);
    const uint32_t baseBhi = smem_u32(sBhi), baseBlo = smem_u32(sBlo);

    for (int k0 = 0; k0 < K; k0 += 32) {
#pragma unroll
        for (int i = 0; i < 16; i += 2) {
            uint32_t h, l;
            cvt2(ra[i], ra[i+1], h, l);
            *(uint32_t*)&sAhi[ar*SPITCH + aks + i] = h;
            *(uint32_t*)&sAlo[ar*SPITCH + aks + i] = l;
        }
#pragma unroll
        for (int i = 0; i < 16; i += 2) {
            uint32_t h, l;
            cvt2(rb[i], rb[i+1], h, l);
            *(uint32_t*)&sBhi[bn*SPITCH + bks + i] = h;
            *(uint32_t*)&sBlo[bn*SPITCH + bks + i] = l;
        }
        __syncthreads();

        if (k0 + 32 < K) {
            const float* Ag2 = Ag + k0 + 32;
            const float* Wg2 = Wg + (size_t)(k0 + 32) * N;
#pragma unroll
            for (int i = 0; i < 4; i++) *(float4*)(ra + 4*i) = *(const float4*)(Ag2 + 4*i);
#pragma unroll
            for (int i = 0; i < 16; i++) rb[i] = Wg2[(size_t)i * N];
        }

#pragma unroll
        for (int ks = 0; ks < 2; ks++) {
            uint32_t ahi[2][4], alo[2][4];
#pragma unroll
            for (int mt = 0; mt < 2; mt++) {
                int row = m0w + mt*16 + r8 + (q & 1)*8;
                int col = ks*16 + (q >> 1)*8;
                uint32_t off = (uint32_t)(row*SPITCH + col) * 2;
                ldm4(baseAhi + off, ahi[mt]);
                ldm4(baseAlo + off, alo[mt]);
            }
            uint32_t bhi[8][2], blo[8][2];
#pragma unroll
            for (int bt = 0; bt < 4; bt++) {
                int row = n0w + bt*16 + r8 + (q >> 1)*8;
                int col = ks*16 + (q & 1)*8;
                uint32_t off = (uint32_t)(row*SPITCH + col) * 2;
                uint32_t tmp[4];
                ldm4(baseBhi + off, tmp);
                bhi[bt*2][0]=tmp[0]; bhi[bt*2][1]=tmp[1];
                bhi[bt*2+1][0]=tmp[2]; bhi[bt*2+1][1]=tmp[3];
                ldm4(baseBlo + off, tmp);
                blo[bt*2][0]=tmp[0]; blo[bt*2][1]=tmp[1];
                blo[bt*2+1][0]=tmp[2]; blo[bt*2+1][1]=tmp[3];
            }
#pragma unroll
            for (int mt = 0; mt < 2; mt++)
#pragma unroll
                for (int nt = 0; nt < 8; nt++) {
                    mma16816(acc[mt][nt], ahi[mt], bhi[nt]);
                    mma16816(acc[mt][nt], ahi[mt], blo[nt]);
                    mma16816(acc[mt][nt], alo[mt], bhi[nt]);
                }
        }
        __syncthreads();
    }

#pragma unroll
    for (int mt = 0; mt < 2; mt++) {
        int m = row0 + m0w + mt*16 + lane/4;
#pragma unroll
        for (int nt = 0; nt < 8; nt++) {
            int n = col0 + n0w + nt*8 + (lane & 3)*2;
            float2 b2 = *(const float2*)(bias + n);
            float* Cp0 = C + (size_t)m * N + n;
            float* Cp1 = Cp0 + (size_t)8 * N;
            Cp0[0] = acc[mt][nt][0] + b2.x;  Cp0[1] = acc[mt][nt][1] + b2.y;
            Cp1[0] = acc[mt][nt][2] + b2.x;  Cp1[1] = acc[mt][nt][3] + b2.y;
        }
    }
}

// fused Q/K/V/KR projections: blockIdx.z selects which GEMM
__global__ __launch_bounds__(256, 1)
void proj_fused(const float* __restrict__ x,   const float* __restrict__ pos,
                const float* __restrict__ Wq,  const float* __restrict__ bq,
                const float* __restrict__ Wk,  const float* __restrict__ bk,
                const float* __restrict__ Wv,  const float* __restrict__ bv,
                const float* __restrict__ Wkr, const float* __restrict__ bkr,
                float* pQ, float* pK, float* pV, float* pKR)
{
    const int z = blockIdx.z;
    const int row0 = blockIdx.y << 7, col0 = blockIdx.x << 7;
    if (z == 3 && row0 >= Sn) return;
    const float* A; const float* W; const float* bias; float* C;
    if      (z == 0) { A = x;   W = Wq;  bias = bq;  C = pQ;  }
    else if (z == 1) { A = x;   W = Wk;  bias = bk;  C = pK;  }
    else if (z == 2) { A = x;   W = Wv;  bias = bv;  C = pV;  }
    else             { A = pos; W = Wkr; bias = bkr; C = pKR; }
    gemm_body(A, W, bias, C, Dn, Dn, row0, col0);
}

__global__ __launch_bounds__(256, 1)
void mma_gemm_nn(const float* __restrict__ A, const float* __restrict__ W,
                 const float* __restrict__ bias, float* __restrict__ C)
{
    gemm_body(A, W, bias, C, Dn, Dn, blockIdx.y << 7, blockIdx.x << 7);
}

// ---------------------------------------------------------------------------
// bf16x3 NT GEMM:  T[bh] = Q_bh [S,64] @ KR_h^T  (unchanged, passing)
// ---------------------------------------------------------------------------
__global__ __launch_bounds__(256, 1)
void mma_gemm_t()
{
    __shared__ __align__(16) uint16_t sAhi[128*SPITCH];
    __shared__ __align__(16) uint16_t sAlo[128*SPITCH];
    __shared__ __align__(16) uint16_t sBhi[128*SPITCH];
    __shared__ __align__(16) uint16_t sBlo[128*SPITCH];

    const int t = threadIdx.x, lane = t & 31, wid = t >> 5;
    const int bh = blockIdx.z, b = bh >> 4, h = bh & 15;
    const int row0 = blockIdx.y << 7, col0 = blockIdx.x << 7;
    const int m0w = (wid & 3) << 5, n0w = (wid >> 2) << 6;
    const int q = lane >> 3, r8 = lane & 7;

    const float* Aq = g_Q  + (size_t)b * Sn * Dn + h * DHn;
    const float* Bm = g_KR + h * DHn;
    float* C = g_T + (size_t)bh * Sn * Sn;

    const int ar = t >> 1, aks = (t & 1) << 4;

    float acc[2][8][4];
#pragma unroll
    for (int mt = 0; mt < 2; mt++)
#pragma unroll
        for (int nt = 0; nt < 8; nt++)
#pragma unroll
            for (int c = 0; c < 4; c++) acc[mt][nt][c] = 0.f;

    const uint32_t baseAhi = smem_u32(sAhi), baseAlo = smem_u32(sAlo);
    const uint32_t baseBhi = smem_u32(sBhi), baseBlo = smem_u32(sBlo);

    for (int k0 = 0; k0 < DHn; k0 += 32) {
        const float* Ap = Aq + (size_t)(row0 + ar) * Dn + k0 + aks;
        const float* Bp = Bm + (size_t)(col0 + ar) * Dn + k0 + aks;
#pragma unroll
        for (int i = 0; i < 16; i += 4) {
            float4 va = *(const float4*)(Ap + i);
            uint32_t h0, l0, h1, l1;
            cvt2(va.x, va.y, h0, l0); cvt2(va.z, va.w, h1, l1);
            *(uint32_t*)&sAhi[ar*SPITCH + aks + i]     = h0;
            *(uint32_t*)&sAlo[ar*SPITCH + aks + i]     = l0;
            *(uint32_t*)&sAhi[ar*SPITCH + aks + i + 2] = h1;
            *(uint32_t*)&sAlo[ar*SPITCH + aks + i + 2] = l1;
            float4 vb = *(const float4*)(Bp + i);
            cvt2(vb.x, vb.y, h0, l0); cvt2(vb.z, vb.w, h1, l1);
            *(uint32_t*)&sBhi[ar*SPITCH + aks + i]     = h0;
            *(uint32_t*)&sBlo[ar*SPITCH + aks + i]     = l0;
            *(uint32_t*)&sBhi[ar*SPITCH + aks + i + 2] = h1;
            *(uint32_t*)&sBlo[ar*SPITCH + aks + i + 2] = l1;
        }
        __syncthreads();

#pragma unroll
        for (int ks = 0; ks < 2; ks++) {
            uint32_t ahi[2][4], alo[2][4];
#pragma unroll
            for (int mt = 0; mt < 2; mt++) {
                int row = m0w + mt*16 + r8 + (q & 1)*8;
                int col = ks*16 + (q >> 1)*8;
                uint32_t off = (uint32_t)(row*SPITCH + col) * 2;
                ldm4(baseAhi + off, ahi[mt]);
                ldm4(baseAlo + off, alo[mt]);
            }
            uint32_t bhi[8][2], blo[8][2];
#pragma unroll
            for (int bt = 0; bt < 4; bt++) {
                int row = n0w + bt*16 + r8 + (q >> 1)*8;
                int col = ks*16 + (q & 1)*8;
                uint32_t off = (uint32_t)(row*SPITCH + col) * 2;
                uint32_t tmp[4];
                ldm4(baseBhi + off, tmp);
                bhi[bt*2][0]=tmp[0]; bhi[bt*2][1]=tmp[1];
                bhi[bt*2+1][0]=tmp[2]; bhi[bt*2+1][1]=tmp[3];
                ldm4(baseBlo + off, tmp);
                blo[bt*2][0]=tmp[0]; blo[bt*2][1]=tmp[1];
                blo[bt*2+1][0]=tmp[2]; blo[bt*2+1][1]=tmp[3];
            }
#pragma unroll
            for (int mt = 0; mt < 2; mt++)
#pragma unroll
                for (int nt = 0; nt < 8; nt++) {
                    mma16816(acc[mt][nt], ahi[mt], bhi[nt]);
                    mma16816(acc[mt][nt], ahi[mt], blo[nt]);
                    mma16816(acc[mt][nt], alo[mt], bhi[nt]);
                }
        }
        __syncthreads();
    }

#pragma unroll
    for (int mt = 0; mt < 2; mt++) {
        int m = row0 + m0w + mt*16 + lane/4;
#pragma unroll
        for (int nt = 0; nt < 8; nt++) {
            int n = col0 + n0w + nt*8 + (lane & 3)*2;
            float* Cp0 = C + (size_t)m * Sn + n;
            float* Cp1 = Cp0 + (size_t)8 * Sn;
            Cp0[0] = acc[mt][nt][0];  Cp0[1] = acc[mt][nt][1];
            Cp1[0] = acc[mt][nt][2];  Cp1[1] = acc[mt][nt][3];
        }
    }
}

// ---------------------------------------------------------------------------
// Flash attention v2: 32-j sub-passes (low reg pressure), ldmatrix.trans V,
// BD prefetch overlapping S-MMAs.
// ---------------------------------------------------------------------------
#define FP 72
#define FQHI 0
#define FQLO (128*FP)
#define FKHI (2*128*FP)
#define FKLO (2*128*FP + 64*FP)
#define FVHI (2*128*FP + 2*64*FP)
#define FVLO (2*128*FP + 3*64*FP)
#define FLASH_SMEM ((2*128*FP + 4*64*FP) * 2)

__global__ __launch_bounds__(256, 1)
void flash_mma(const float* __restrict__ u)
{
    extern __shared__ __align__(16) uint16_t fsm[];
    const int t = threadIdx.x, lane = t & 31, w = t >> 5;
    const int q = lane >> 3, r8 = lane & 7;
    const int r = lane >> 2, qq = lane & 3;
    const int bh = blockIdx.y, b = bh >> 4, h = bh & 15;
    const int i0 = blockIdx.x << 7;

    const float* Qg = g_Q + ((size_t)b*Sn + i0)*Dn + h*DHn;
    const float* Kg = g_K + (size_t)b*Sn*Dn + h*DHn;
    const float* Vg = g_V + (size_t)b*Sn*Dn + h*DHn;
    const float* Tg = g_T + (size_t)bh*Sn*Sn;

    const uint32_t base = smem_u32(fsm);

    // ---- stage Q: (q + u)*0.125 -> hi/lo
    {
        const int qr = t >> 1, cb = (t & 1) << 5;
        const float* Qp = Qg + (size_t)qr * Dn + cb;
        const float* up = u + h*DHn + cb;
#pragma unroll
        for (int i = 0; i < 32; i += 4) {
            float4 v = *(const float4*)(Qp + i);
            float4 uv = *(const float4*)(up + i);
            uint32_t h0, l0_, h1, l1_;
            cvt2((v.x+uv.x)*0.125f, (v.y+uv.y)*0.125f, h0, l0_);
            cvt2((v.z+uv.z)*0.125f, (v.w+uv.w)*0.125f, h1, l1_);
            *(uint32_t*)&fsm[FQHI + qr*FP + cb + i]     = h0;
            *(uint32_t*)&fsm[FQLO + qr*FP + cb + i]     = l0_;
            *(uint32_t*)&fsm[FQHI + qr*FP + cb + i + 2] = h1;
            *(uint32_t*)&fsm[FQLO + qr*FP + cb + i + 2] = l1_;
        }
    }
    __syncthreads();

    uint32_t qhi[4][4], qlo[4][4];
#pragma unroll
    for (int ks = 0; ks < 4; ks++) {
        int row = w*16 + r8 + (q & 1)*8;
        int col = ks*16 + (q >> 1)*8;
        uint32_t off = (uint32_t)(row*FP + col) * 2;
        ldm4(base + (FQHI*2) + off, qhi[ks]);
        ldm4(base + (FQLO*2) + off, qlo[ks]);
    }

    float pacc[8][4];
#pragma unroll
    for (int dt = 0; dt < 8; dt++)
#pragma unroll
        for (int c = 0; c < 4; c++) pacc[dt][c] = 0.f;
    float m0 = -1e30f, m1 = -1e30f, l0 = 0.f, l1 = 0.f;

    const int i_r  = i0 + w*16 + r;
    const int i_r8 = i_r + 8;

    for (int j0 = 0; j0 < Sn; j0 += 64) {
        // ---- stage K and V, both row-major [j][d], hi/lo
        {
            const int jr = t >> 2, cb = (t & 3) << 4;
            const float* Kp = Kg + (size_t)(j0 + jr) * Dn + cb;
            const float* Vp = Vg + (size_t)(j0 + jr) * Dn + cb;
#pragma unroll
            for (int i = 0; i < 16; i += 4) {
                float4 kv = *(const float4*)(Kp + i);
                uint32_t h0, l0_, h1, l1_;
                cvt2(kv.x, kv.y, h0, l0_); cvt2(kv.z, kv.w, h1, l1_);
                *(uint32_t*)&fsm[FKHI + jr*FP + cb + i]     = h0;
                *(uint32_t*)&fsm[FKLO + jr*FP + cb + i]     = l0_;
                *(uint32_t*)&fsm[FKHI + jr*FP + cb + i + 2] = h1;
                *(uint32_t*)&fsm[FKLO + jr*FP + cb + i + 2] = l1_;
                float4 vv = *(const float4*)(Vp + i);
                cvt2(vv.x, vv.y, h0, l0_); cvt2(vv.z, vv.w, h1, l1_);
                *(uint32_t*)&fsm[FVHI + jr*FP + cb + i]     = h0;
                *(uint32_t*)&fsm[FVLO + jr*FP + cb + i]     = l0_;
                *(uint32_t*)&fsm[FVHI + jr*FP + cb + i + 2] = h1;
                *(uint32_t*)&fsm[FVLO + jr*FP + cb + i + 2] = l1_;
            }
        }
        __syncthreads();

#pragma unroll
        for (int sub = 0; sub < 2; sub++) {
            const int j1 = j0 + (sub << 5);

            // ---- BD prefetch (overlaps the S-MMAs below)
            float bd[4][4];
#pragma unroll
            for (int nt = 0; nt < 4; nt++) {
                int jb = j1 + nt*8 + 2*qq;
#pragma unroll
                for (int e = 0; e < 4; e++) {
                    int i = (e < 2) ? i_r : i_r8;
                    int j = jb + (e & 1);
                    int ir = (j <= i) ? i : i + 1;
                    int ic = (j <= i) ? (Sn - 1 - i + j) : (j - i - 2);
                    float v = __ldg(Tg + (size_t)ir * Sn + ic);
                    bd[nt][e] = (j == i + 1) ? 0.f : v;
                }
            }

            // ---- S = Qs @ K^T (bf16x3)
            float sacc[4][4];
#pragma unroll
            for (int nt = 0; nt < 4; nt++)
#pragma unroll
                for (int c = 0; c < 4; c++) sacc[nt][c] = 0.f;

#pragma unroll
            for (int ks = 0; ks < 4; ks++) {
                uint32_t kh[4][2], kl[4][2];
#pragma unroll
                for (int bt = 0; bt < 2; bt++) {
                    int row = (sub << 5) + bt*16 + r8 + (q >> 1)*8;
                    int col = ks*16 + (q & 1)*8;
                    uint32_t off = (uint32_t)(row*FP + col) * 2;
                    uint32_t tmp[4];
                    ldm4(base + (FKHI*2) + off, tmp);
                    kh[bt*2][0]=tmp[0]; kh[bt*2][1]=tmp[1];
                    kh[bt*2+1][0]=tmp[2]; kh[bt*2+1][1]=tmp[3];
                    ldm4(base + (FKLO*2) + off, tmp);
                    kl[bt*2][0]=tmp[0]; kl[bt*2][1]=tmp[1];
                    kl[bt*2+1][0]=tmp[2]; kl[bt*2+1][1]=tmp[3];
                }
#pragma unroll
                for (int nt = 0; nt < 4; nt++) {
                    mma16816(sacc[nt], qhi[ks], kh[nt]);
                    mma16816(sacc[nt], qhi[ks], kl[nt]);
                    mma16816(sacc[nt], qlo[ks], kh[nt]);
                }
            }

            // ---- add BD, online softmax
            float ml0 = -1e30f, ml1 = -1e30f;
#pragma unroll
            for (int nt = 0; nt < 4; nt++)
#pragma unroll
                for (int e = 0; e < 4; e++) {
                    float sv = fmaf(bd[nt][e], 0.125f, sacc[nt][e]);
                    sacc[nt][e] = sv;
                    if (e < 2) ml0 = fmaxf(ml0, sv); else ml1 = fmaxf(ml1, sv);
                }
            ml0 = fmaxf(ml0, __shfl_xor_sync(0xFFFFFFFFu, ml0, 1));
            ml0 = fmaxf(ml0, __shfl_xor_sync(0xFFFFFFFFu, ml0, 2));
            ml1 = fmaxf(ml1, __shfl_xor_sync(0xFFFFFFFFu, ml1, 1));
            ml1 = fmaxf(ml1, __shfl_xor_sync(0xFFFFFFFFu, ml1, 2));

            float mn0 = fmaxf(m0, ml0), mn1 = fmaxf(m1, ml1);
            float f0 = __expf(m0 - mn0), f1 = __expf(m1 - mn1);
            m0 = mn0; m1 = mn1;

            float ls0 = 0.f, ls1 = 0.f;
#pragma unroll
            for (int nt = 0; nt < 4; nt++) {
                float p0 = __expf(sacc[nt][0] - m0);
                float p1 = __expf(sacc[nt][1] - m0);
                float p2 = __expf(sacc[nt][2] - m1);
                float p3 = __expf(sacc[nt][3] - m1);
                sacc[nt][0] = p0; sacc[nt][1] = p1; sacc[nt][2] = p2; sacc[nt][3] = p3;
                ls0 += p0 + p1;  ls1 += p2 + p3;
            }
            ls0 += __shfl_xor_sync(0xFFFFFFFFu, ls0, 1);
            ls0 += __shfl_xor_sync(0xFFFFFFFFu, ls0, 2);
            ls1 += __shfl_xor_sync(0xFFFFFFFFu, ls1, 1);
            ls1 += __shfl_xor_sync(0xFFFFFFFFu, ls1, 2);
            l0 = l0 * f0 + ls0;
            l1 = l1 * f1 + ls1;

#pragma unroll
            for (int dt = 0; dt < 8; dt++) {
                pacc[dt][0] *= f0; pacc[dt][1] *= f0;
                pacc[dt][2] *= f1; pacc[dt][3] *= f1;
            }

            // ---- pack P (C-frag pair -> A-frag)
            uint32_t phi[2][4], plo[2][4];
#pragma unroll
            for (int ks = 0; ks < 2; ks++) {
                cvt2(sacc[2*ks][0],   sacc[2*ks][1],   phi[ks][0], plo[ks][0]);
                cvt2(sacc[2*ks][2],   sacc[2*ks][3],   phi[ks][1], plo[ks][1]);
                cvt2(sacc[2*ks+1][0], sacc[2*ks+1][1], phi[ks][2], plo[ks][2]);
                cvt2(sacc[2*ks+1][2], sacc[2*ks+1][3], phi[ks][3], plo[ks][3]);
            }

            // ---- pacc += P @ V  (V B-frags via ldmatrix.trans on row-major V)
#pragma unroll
            for (int ks = 0; ks < 2; ks++) {
                uint32_t vh[8][2], vl[8][2];
#pragma unroll
                for (int dt2 = 0; dt2 < 4; dt2++) {
                    int krow = (sub << 5) + ks*16 + (lane & 7) + ((lane >> 3) & 1)*8;
                    int ncol = dt2*16 + ((lane >> 4) << 3);
                    uint32_t off = (uint32_t)(krow*FP + ncol) * 2;
                    uint32_t tmp[4];
                    ldm4t(base + (FVHI*2) + off, tmp);
                    vh[dt2*2][0]=tmp[0]; vh[dt2*2][1]=tmp[1];
                    vh[dt2*2+1][0]=tmp[2]; vh[dt2*2+1][1]=tmp[3];
                    ldm4t(base + (FVLO*2) + off, tmp);
                    vl[dt2*2][0]=tmp[0]; vl[dt2*2][1]=tmp[1];
                    vl[dt2*2+1][0]=tmp[2]; vl[dt2*2+1][1]=tmp[3];
                }
#pragma unroll
                for (int dt = 0; dt < 8; dt++) {
                    mma16816(pacc[dt], phi[ks], vh[dt]);
                    mma16816(pacc[dt], phi[ks], vl[dt]);
                    mma16816(pacc[dt], plo[ks], vh[dt]);
                }
            }
        }
        __syncthreads();
    }

    // ---- normalize & write out
    float inv0 = 1.f / l0, inv1 = 1.f / l1;
    float* Og = g_AO + (size_t)b*Sn*Dn + h*DHn;
#pragma unroll
    for (int dt = 0; dt < 8; dt++) {
        int d = dt*8 + 2*qq;
        float2 o0 = make_float2(pacc[dt][0]*inv0, pacc[dt][1]*inv0);
        float2 o1 = make_float2(pacc[dt][2]*inv1, pacc[dt][3]*inv1);
        *(float2*)(Og + (size_t)i_r  * Dn + d) = o0;
        *(float2*)(Og + (size_t)i_r8 * Dn + d) = o1;
    }
}

// ---------------------------------------------------------------------------
// Launch
// ---------------------------------------------------------------------------
extern "C" void kernel_launch(void* const* d_in, const int* in_sizes, int n_in,
                              void* d_out, int out_size)
{
    const float* x   = (const float*)d_in[0];
    const float* pos = (const float*)d_in[1];
    const float* Wq  = (const float*)d_in[2];
    const float* bq  = (const float*)d_in[3];
    const float* Wk  = (const float*)d_in[4];
    const float* bk  = (const float*)d_in[5];
    const float* Wv  = (const float*)d_in[6];
    const float* bv  = (const float*)d_in[7];
    const float* Wo  = (const float*)d_in[8];
    const float* bo  = (const float*)d_in[9];
    const float* Wkr = (const float*)d_in[10];
    const float* bkr = (const float*)d_in[11];
    const float* u   = (const float*)d_in[12];
    // d_in[13] (v) unused: GH term is per-row constant -> softmax-invariant.

    float *pQ, *pK, *pV, *pKR, *pAO;
    cudaGetSymbolAddress((void**)&pQ,  g_Q);
    cudaGetSymbolAddress((void**)&pK,  g_K);
    cudaGetSymbolAddress((void**)&pV,  g_V);
    cudaGetSymbolAddress((void**)&pKR, g_KR);
    cudaGetSymbolAddress((void**)&pAO, g_AO);

    cudaFuncSetAttribute(flash_mma, cudaFuncAttributeMaxDynamicSharedMemorySize, FLASH_SMEM);

    dim3 thr(256);
    proj_fused<<<dim3(Dn/128, (Bn*Sn)/128, 4), thr>>>(
        x, pos, Wq, bq, Wk, bk, Wv, bv, Wkr, bkr, pQ, pK, pV, pKR);
    mma_gemm_t<<<dim3(Sn/128, Sn/128, BHn), thr>>>();
    flash_mma<<<dim3(Sn/128, BHn), thr, FLASH_SMEM>>>(u);
    mma_gemm_nn<<<dim3(Dn/128, (Bn*Sn)/128), thr>>>(pAO, Wo, bo, (float*)d_out);
}

// round 6
// speedup vs baseline: 2.2918x; 1.0849x over previous
#include <cuda_runtime.h>
#include <cuda_bf16.h>
#include <stdint.h>

// Problem constants
#define Bn  2
#define Sn  2048
#define Dn  1024
#define Hn  16
#define DHn 64
#define BHn (Bn*Hn)
#define CSC 0.18033688f   // 0.125 * log2(e) — softmax done in exp2 domain

// ---------------------------------------------------------------------------
// Scratch (static __device__ — no runtime allocation)
// Q/K/V/KR stored ONLY as bf16 hi/lo planes (written by projection epilogue).
// ---------------------------------------------------------------------------
__device__ uint16_t g_Qh[(size_t)Bn*Sn*Dn], g_Ql[(size_t)Bn*Sn*Dn];
__device__ uint16_t g_Kh[(size_t)Bn*Sn*Dn], g_Kl[(size_t)Bn*Sn*Dn];
__device__ uint16_t g_Vh[(size_t)Bn*Sn*Dn], g_Vl[(size_t)Bn*Sn*Dn];
__device__ uint16_t g_KRh[(size_t)Sn*Dn],   g_KRl[(size_t)Sn*Dn];
__device__ float    g_T [(size_t)BHn*Sn*Sn];   // 536 MB : T = Q @ KR^T per (b,h)
__device__ float    g_AO[(size_t)Bn*Sn*Dn];

// ---------------------------------------------------------------------------
// Helpers
// ---------------------------------------------------------------------------
__device__ __forceinline__ uint32_t smem_u32(const void* p) {
    uint32_t a;
    asm("{ .reg .u64 t; cvta.to.shared.u64 t, %1; cvt.u32.u64 %0, t; }"
        : "=r"(a) : "l"(p));
    return a;
}

__device__ __forceinline__ void ldm4(uint32_t addr, uint32_t* r) {
    asm volatile("ldmatrix.sync.aligned.m8n8.x4.shared.b16 {%0,%1,%2,%3}, [%4];"
        : "=r"(r[0]), "=r"(r[1]), "=r"(r[2]), "=r"(r[3]) : "r"(addr));
}

__device__ __forceinline__ void ldm4t(uint32_t addr, uint32_t* r) {
    asm volatile("ldmatrix.sync.aligned.m8n8.x4.trans.shared.b16 {%0,%1,%2,%3}, [%4];"
        : "=r"(r[0]), "=r"(r[1]), "=r"(r[2]), "=r"(r[3]) : "r"(addr));
}

__device__ __forceinline__ void mma16816(float* c, const uint32_t* a, const uint32_t* b) {
    asm volatile(
        "mma.sync.aligned.m16n8k16.row.col.f32.bf16.bf16.f32 "
        "{%0,%1,%2,%3}, {%4,%5,%6,%7}, {%8,%9}, {%0,%1,%2,%3};"
        : "+f"(c[0]), "+f"(c[1]), "+f"(c[2]), "+f"(c[3])
        : "r"(a[0]), "r"(a[1]), "r"(a[2]), "r"(a[3]), "r"(b[0]), "r"(b[1]));
}

__device__ __forceinline__ float ex2f(float x) {
    float y; asm("ex2.approx.ftz.f32 %0, %1;" : "=f"(y) : "f"(x)); return y;
}

__device__ __forceinline__ void cvt2(float x0, float x1, uint32_t& hi, uint32_t& lo) {
    __nv_bfloat16 h0 = __float2bfloat16(x0);
    __nv_bfloat16 h1 = __float2bfloat16(x1);
    __nv_bfloat16 l0 = __float2bfloat16(x0 - __bfloat162float(h0));
    __nv_bfloat16 l1 = __float2bfloat16(x1 - __bfloat162float(h1));
    hi = (uint32_t)__bfloat16_as_ushort(h0) | ((uint32_t)__bfloat16_as_ushort(h1) << 16);
    lo = (uint32_t)__bfloat16_as_ushort(l0) | ((uint32_t)__bfloat16_as_ushort(l1) << 16);
}

__device__ __forceinline__ float2 unpack_bf2(uint32_t w) {
    return make_float2(
        __bfloat162float(__ushort_as_bfloat16((unsigned short)(w & 0xFFFFu))),
        __bfloat162float(__ushort_as_bfloat16((unsigned short)(w >> 16))));
}

// ---------------------------------------------------------------------------
// NN GEMM (bf16x3, double-buffered smem): C = A@W + bias
// fp32 A/W in; out = fp32 C (PLANES=false) or bf16 hi/lo planes (PLANES=true)
// ---------------------------------------------------------------------------
#define SPITCH 40
#define GOA_HI 0
#define GOA_LO 5120
#define GOB_HI 10240
#define GOB_LO 15360
#define GSTAGE_SZ 20480              // b16 per stage
#define GEMM_SMEM (2*GSTAGE_SZ*2)    // bytes

__device__ __forceinline__
void gemm_stage(uint16_t* sm, const float* ra, const float* rb,
                int ar, int aks, int bn, int bks)
{
#pragma unroll
    for (int i = 0; i < 16; i += 2) {
        uint32_t h, l;
        cvt2(ra[i], ra[i+1], h, l);
        *(uint32_t*)&sm[GOA_HI + ar*SPITCH + aks + i] = h;
        *(uint32_t*)&sm[GOA_LO + ar*SPITCH + aks + i] = l;
        cvt2(rb[i], rb[i+1], h, l);
        *(uint32_t*)&sm[GOB_HI + bn*SPITCH + bks + i] = h;
        *(uint32_t*)&sm[GOB_LO + bn*SPITCH + bks + i] = l;
    }
}

template<bool PLANES>
__device__ __forceinline__
void gemm_body(const float* __restrict__ A, const float* __restrict__ W,
               const float* __restrict__ bias, float* __restrict__ C,
               uint16_t* __restrict__ Chi, uint16_t* __restrict__ Clo,
               int N, int K, int row0, int col0, uint16_t* sm)
{
    const int t = threadIdx.x, lane = t & 31, wid = t >> 5;
    const int m0w = (wid & 3) << 5, n0w = (wid >> 2) << 6;
    const int q = lane >> 3, r8 = lane & 7;
    const int ar = t >> 1, aks = (t & 1) << 4;
    const int bn = t & 127, bks = (t >> 7) << 4;
    const float* Ag = A + (size_t)(row0 + ar) * K + aks;
    const float* Wg = W + (size_t)bks * N + col0 + bn;

    float ra[16], rb[16];
#pragma unroll
    for (int i = 0; i < 4; i++) *(float4*)(ra + 4*i) = *(const float4*)(Ag + 4*i);
#pragma unroll
    for (int i = 0; i < 16; i++) rb[i] = Wg[(size_t)i * N];
    gemm_stage(sm, ra, rb, ar, aks, bn, bks);    // chunk 0 -> buf 0

    const int NC = K >> 5;
    if (NC > 1) {                                 // prefetch chunk 1
        const float* Ag2 = Ag + 32;
        const float* Wg2 = Wg + (size_t)32 * N;
#pragma unroll
        for (int i = 0; i < 4; i++) *(float4*)(ra + 4*i) = *(const float4*)(Ag2 + 4*i);
#pragma unroll
        for (int i = 0; i < 16; i++) rb[i] = Wg2[(size_t)i * N];
    }

    float acc[2][8][4];
#pragma unroll
    for (int mt = 0; mt < 2; mt++)
#pragma unroll
        for (int nt = 0; nt < 8; nt++)
#pragma unroll
            for (int c = 0; c < 4; c++) acc[mt][nt][c] = 0.f;

    __syncthreads();

    for (int c = 0; c < NC; c++) {
        uint16_t* cur = sm + (c & 1) * GSTAGE_SZ;
        if (c + 1 < NC) {
            gemm_stage(sm + ((c + 1) & 1) * GSTAGE_SZ, ra, rb, ar, aks, bn, bks);
            if (c + 2 < NC) {
                const float* Ag2 = Ag + (c + 2) * 32;
                const float* Wg2 = Wg + (size_t)(c + 2) * 32 * N;
#pragma unroll
                for (int i = 0; i < 4; i++) *(float4*)(ra + 4*i) = *(const float4*)(Ag2 + 4*i);
#pragma unroll
                for (int i = 0; i < 16; i++) rb[i] = Wg2[(size_t)i * N];
            }
        }
        const uint32_t cb = smem_u32(cur);
#pragma unroll
        for (int ks = 0; ks < 2; ks++) {
            uint32_t ahi[2][4], alo[2][4];
#pragma unroll
            for (int mt = 0; mt < 2; mt++) {
                int row = m0w + mt*16 + r8 + (q & 1)*8;
                int col = ks*16 + (q >> 1)*8;
                uint32_t off = (uint32_t)(row*SPITCH + col) * 2;
                ldm4(cb + GOA_HI*2 + off, ahi[mt]);
                ldm4(cb + GOA_LO*2 + off, alo[mt]);
            }
            uint32_t bhi[8][2], blo[8][2];
#pragma unroll
            for (int bt = 0; bt < 4; bt++) {
                int row = n0w + bt*16 + r8 + (q >> 1)*8;
                int col = ks*16 + (q & 1)*8;
                uint32_t off = (uint32_t)(row*SPITCH + col) * 2;
                uint32_t tmp[4];
                ldm4(cb + GOB_HI*2 + off, tmp);
                bhi[bt*2][0]=tmp[0]; bhi[bt*2][1]=tmp[1];
                bhi[bt*2+1][0]=tmp[2]; bhi[bt*2+1][1]=tmp[3];
                ldm4(cb + GOB_LO*2 + off, tmp);
                blo[bt*2][0]=tmp[0]; blo[bt*2][1]=tmp[1];
                blo[bt*2+1][0]=tmp[2]; blo[bt*2+1][1]=tmp[3];
            }
#pragma unroll
            for (int mt = 0; mt < 2; mt++)
#pragma unroll
                for (int nt = 0; nt < 8; nt++) {
                    mma16816(acc[mt][nt], ahi[mt], bhi[nt]);
                    mma16816(acc[mt][nt], ahi[mt], blo[nt]);
                    mma16816(acc[mt][nt], alo[mt], bhi[nt]);
                }
        }
        __syncthreads();
    }

#pragma unroll
    for (int mt = 0; mt < 2; mt++) {
        int m = row0 + m0w + mt*16 + lane/4;
#pragma unroll
        for (int nt = 0; nt < 8; nt++) {
            int n = col0 + n0w + nt*8 + (lane & 3)*2;
            float2 b2 = *(const float2*)(bias + n);
            float v0 = acc[mt][nt][0] + b2.x, v1 = acc[mt][nt][1] + b2.y;
            float v2 = acc[mt][nt][2] + b2.x, v3 = acc[mt][nt][3] + b2.y;
            if (PLANES) {
                uint32_t h, l;
                cvt2(v0, v1, h, l);
                *(uint32_t*)&Chi[(size_t)m*N + n] = h;
                *(uint32_t*)&Clo[(size_t)m*N + n] = l;
                cvt2(v2, v3, h, l);
                *(uint32_t*)&Chi[(size_t)(m+8)*N + n] = h;
                *(uint32_t*)&Clo[(size_t)(m+8)*N + n] = l;
            } else {
                float* Cp0 = C + (size_t)m * N + n;
                float* Cp1 = Cp0 + (size_t)8 * N;
                Cp0[0] = v0;  Cp0[1] = v1;
                Cp1[0] = v2;  Cp1[1] = v3;
            }
        }
    }
}

// fused Q/K/V/KR projections -> bf16 hi/lo planes
__global__ __launch_bounds__(256, 1)
void proj_fused(const float* __restrict__ x,   const float* __restrict__ pos,
                const float* __restrict__ Wq,  const float* __restrict__ bq,
                const float* __restrict__ Wk,  const float* __restrict__ bk,
                const float* __restrict__ Wv,  const float* __restrict__ bv,
                const float* __restrict__ Wkr, const float* __restrict__ bkr)
{
    extern __shared__ uint16_t gsm[];
    const int z = blockIdx.z;
    const int row0 = blockIdx.y << 7, col0 = blockIdx.x << 7;
    if (z == 3 && row0 >= Sn) return;
    const float *A, *W, *bias; uint16_t *Chi, *Clo;
    if      (z == 0) { A = x;   W = Wq;  bias = bq;  Chi = g_Qh;  Clo = g_Ql;  }
    else if (z == 1) { A = x;   W = Wk;  bias = bk;  Chi = g_Kh;  Clo = g_Kl;  }
    else if (z == 2) { A = x;   W = Wv;  bias = bv;  Chi = g_Vh;  Clo = g_Vl;  }
    else             { A = pos; W = Wkr; bias = bkr; Chi = g_KRh; Clo = g_KRl; }
    gemm_body<true>(A, W, bias, nullptr, Chi, Clo, Dn, Dn, row0, col0, gsm);
}

// Wo GEMM: fp32 AO @ Wo + bo -> fp32 out
__global__ __launch_bounds__(256, 1)
void mma_gemm_wo(const float* __restrict__ W, const float* __restrict__ bias,
                 float* __restrict__ C)
{
    extern __shared__ uint16_t gsm[];
    gemm_body<false>(g_AO, W, bias, C, nullptr, nullptr, Dn, Dn,
                     blockIdx.y << 7, blockIdx.x << 7, gsm);
}

// ---------------------------------------------------------------------------
// NT GEMM from planes:  T[bh] = Q_bh [S,64] @ KR_h^T.  Single stage (K=64).
// ---------------------------------------------------------------------------
#define TP 72
#define TAH 0
#define TAL (128*TP)
#define TBH (2*128*TP)
#define TBL (3*128*TP)
#define TSMEM (4*128*TP*2)

__global__ __launch_bounds__(256, 1)
void mma_gemm_t()
{
    extern __shared__ uint16_t tsm[];
    const int t = threadIdx.x, lane = t & 31, wid = t >> 5;
    const int bh = blockIdx.z, b = bh >> 4, h = bh & 15;
    const int row0 = blockIdx.y << 7, col0 = blockIdx.x << 7;
    const int m0w = (wid & 3) << 5, n0w = (wid >> 2) << 6;
    const int q = lane >> 3, r8 = lane & 7;

    float* C = g_T + (size_t)bh * Sn * Sn;

    // stage: copy bf16 planes (no conversion)
    {
        const int r = t >> 1, c = (t & 1) << 5;
        const size_t soA = ((size_t)b*Sn + row0 + r) * Dn + h*DHn + c;
        const size_t soB = ((size_t)col0 + r) * Dn + h*DHn + c;
#pragma unroll
        for (int i = 0; i < 32; i += 8) {
            *(uint4*)&tsm[TAH + r*TP + c + i] = *(const uint4*)(g_Qh  + soA + i);
            *(uint4*)&tsm[TAL + r*TP + c + i] = *(const uint4*)(g_Ql  + soA + i);
            *(uint4*)&tsm[TBH + r*TP + c + i] = *(const uint4*)(g_KRh + soB + i);
            *(uint4*)&tsm[TBL + r*TP + c + i] = *(const uint4*)(g_KRl + soB + i);
        }
    }
    __syncthreads();

    float acc[2][8][4];
#pragma unroll
    for (int mt = 0; mt < 2; mt++)
#pragma unroll
        for (int nt = 0; nt < 8; nt++)
#pragma unroll
            for (int c = 0; c < 4; c++) acc[mt][nt][c] = 0.f;

    const uint32_t cb = smem_u32(tsm);
#pragma unroll
    for (int ks = 0; ks < 4; ks++) {
        uint32_t ahi[2][4], alo[2][4];
#pragma unroll
        for (int mt = 0; mt < 2; mt++) {
            int row = m0w + mt*16 + r8 + (q & 1)*8;
            int col = ks*16 + (q >> 1)*8;
            uint32_t off = (uint32_t)(row*TP + col) * 2;
            ldm4(cb + TAH*2 + off, ahi[mt]);
            ldm4(cb + TAL*2 + off, alo[mt]);
        }
        uint32_t bhi[8][2], blo[8][2];
#pragma unroll
        for (int bt = 0; bt < 4; bt++) {
            int row = n0w + bt*16 + r8 + (q >> 1)*8;
            int col = ks*16 + (q & 1)*8;
            uint32_t off = (uint32_t)(row*TP + col) * 2;
            uint32_t tmp[4];
            ldm4(cb + TBH*2 + off, tmp);
            bhi[bt*2][0]=tmp[0]; bhi[bt*2][1]=tmp[1];
            bhi[bt*2+1][0]=tmp[2]; bhi[bt*2+1][1]=tmp[3];
            ldm4(cb + TBL*2 + off, tmp);
            blo[bt*2][0]=tmp[0]; blo[bt*2][1]=tmp[1];
            blo[bt*2+1][0]=tmp[2]; blo[bt*2+1][1]=tmp[3];
        }
#pragma unroll
        for (int mt = 0; mt < 2; mt++)
#pragma unroll
            for (int nt = 0; nt < 8; nt++) {
                mma16816(acc[mt][nt], ahi[mt], bhi[nt]);
                mma16816(acc[mt][nt], ahi[mt], blo[nt]);
                mma16816(acc[mt][nt], alo[mt], bhi[nt]);
            }
    }

#pragma unroll
    for (int mt = 0; mt < 2; mt++) {
        int m = row0 + m0w + mt*16 + lane/4;
#pragma unroll
        for (int nt = 0; nt < 8; nt++) {
            int n = col0 + n0w + nt*8 + (lane & 3)*2;
            float* Cp0 = C + (size_t)m * Sn + n;
            float* Cp1 = Cp0 + (size_t)8 * Sn;
            Cp0[0] = acc[mt][nt][0];  Cp0[1] = acc[mt][nt][1];
            Cp1[0] = acc[mt][nt][2];  Cp1[1] = acc[mt][nt][3];
        }
    }
}

// ---------------------------------------------------------------------------
// Flash attention: exp2-domain softmax, plane copies for staging, 2 blocks/SM.
//   s(i,j) = (q_i+u)·k_j*CSC + BD(i,j)*CSC ; p = 2^(s-m)
//   BD(i,j): j<=i -> T[i][S-1-i+j] ; j==i+1 -> 0 ; j>i+1 -> T[i+1][j-i-2]
// ---------------------------------------------------------------------------
#define FP 72
#define FQHI 0
#define FQLO (128*FP)
#define FKHI (2*128*FP)
#define FKLO (2*128*FP + 64*FP)
#define FVHI (2*128*FP + 2*64*FP)
#define FVLO (2*128*FP + 3*64*FP)
#define FLASH_SMEM ((2*128*FP + 4*64*FP) * 2)

__global__ __launch_bounds__(256, 2)
void flash_mma(const float* __restrict__ u)
{
    extern __shared__ uint16_t fsm[];
    const int t = threadIdx.x, lane = t & 31, w = t >> 5;
    const int q = lane >> 3, r8 = lane & 7;
    const int r = lane >> 2, qq = lane & 3;
    const int bh = blockIdx.y, b = bh >> 4, h = bh & 15;
    const int i0 = blockIdx.x << 7;

    const float* Tg = g_T + (size_t)bh*Sn*Sn;
    const uint32_t base = smem_u32(fsm);

    // ---- stage Q: reconstruct, (q+u)*CSC, re-split
    {
        const int qr = t >> 1, cb = (t & 1) << 5;
        const size_t so = ((size_t)b*Sn + i0 + qr) * Dn + h*DHn + cb;
        float uu[32];
#pragma unroll
        for (int i = 0; i < 32; i += 4)
            *(float4*)(uu + i) = *(const float4*)(u + h*DHn + cb + i);
#pragma unroll
        for (int i = 0; i < 32; i += 8) {
            uint4 hv = *(const uint4*)(g_Qh + so + i);
            uint4 lv = *(const uint4*)(g_Ql + so + i);
            uint32_t hw[4] = {hv.x, hv.y, hv.z, hv.w};
            uint32_t lw[4] = {lv.x, lv.y, lv.z, lv.w};
#pragma unroll
            for (int k = 0; k < 4; k++) {
                float2 fh = unpack_bf2(hw[k]), fl = unpack_bf2(lw[k]);
                float y0 = (fh.x + fl.x + uu[i + 2*k])     * CSC;
                float y1 = (fh.y + fl.y + uu[i + 2*k + 1]) * CSC;
                uint32_t ho, lo_;
                cvt2(y0, y1, ho, lo_);
                *(uint32_t*)&fsm[FQHI + qr*FP + cb + i + 2*k] = ho;
                *(uint32_t*)&fsm[FQLO + qr*FP + cb + i + 2*k] = lo_;
            }
        }
    }
    __syncthreads();

    float pacc[8][4];
#pragma unroll
    for (int dt = 0; dt < 8; dt++)
#pragma unroll
        for (int c = 0; c < 4; c++) pacc[dt][c] = 0.f;
    float m0 = -1e30f, m1 = -1e30f, l0 = 0.f, l1 = 0.f;

    const int i_r  = i0 + w*16 + r;
    const int i_r8 = i_r + 8;

    for (int j0 = 0; j0 < Sn; j0 += 64) {
        // ---- stage K/V: straight plane copies
        {
            const int jr = t >> 2, cb = (t & 3) << 4;
            const size_t so = ((size_t)b*Sn + j0 + jr) * Dn + h*DHn + cb;
            *(uint4*)&fsm[FKHI + jr*FP + cb]     = *(const uint4*)(g_Kh + so);
            *(uint4*)&fsm[FKHI + jr*FP + cb + 8] = *(const uint4*)(g_Kh + so + 8);
            *(uint4*)&fsm[FKLO + jr*FP + cb]     = *(const uint4*)(g_Kl + so);
            *(uint4*)&fsm[FKLO + jr*FP + cb + 8] = *(const uint4*)(g_Kl + so + 8);
            *(uint4*)&fsm[FVHI + jr*FP + cb]     = *(const uint4*)(g_Vh + so);
            *(uint4*)&fsm[FVHI + jr*FP + cb + 8] = *(const uint4*)(g_Vh + so + 8);
            *(uint4*)&fsm[FVLO + jr*FP + cb]     = *(const uint4*)(g_Vl + so);
            *(uint4*)&fsm[FVLO + jr*FP + cb + 8] = *(const uint4*)(g_Vl + so + 8);
        }
        __syncthreads();

#pragma unroll
        for (int sub = 0; sub < 2; sub++) {
            const int j1 = j0 + (sub << 5);

            // ---- BD prefetch (overlaps S-MMAs)
            float bd[4][4];
#pragma unroll
            for (int nt = 0; nt < 4; nt++) {
                int jb = j1 + nt*8 + 2*qq;
#pragma unroll
                for (int e = 0; e < 4; e++) {
                    int i = (e < 2) ? i_r : i_r8;
                    int j = jb + (e & 1);
                    int ir = (j <= i) ? i : i + 1;
                    int ic = (j <= i) ? (Sn - 1 - i + j) : (j - i - 2);
                    float v = __ldg(Tg + (size_t)ir * Sn + ic);
                    bd[nt][e] = (j == i + 1) ? 0.f : v;
                }
            }

            // ---- Q frags (reloaded per sub-pass to cap register pressure)
            uint32_t qhi[4][4], qlo[4][4];
#pragma unroll
            for (int ks = 0; ks < 4; ks++) {
                int row = w*16 + r8 + (q & 1)*8;
                int col = ks*16 + (q >> 1)*8;
                uint32_t off = (uint32_t)(row*FP + col) * 2;
                ldm4(base + FQHI*2 + off, qhi[ks]);
                ldm4(base + FQLO*2 + off, qlo[ks]);
            }

            // ---- S = Qs @ K^T (bf16x3)
            float sacc[4][4];
#pragma unroll
            for (int nt = 0; nt < 4; nt++)
#pragma unroll
                for (int c = 0; c < 4; c++) sacc[nt][c] = 0.f;

#pragma unroll
            for (int ks = 0; ks < 4; ks++) {
                uint32_t kh[4][2], kl[4][2];
#pragma unroll
                for (int bt = 0; bt < 2; bt++) {
                    int row = (sub << 5) + bt*16 + r8 + (q >> 1)*8;
                    int col = ks*16 + (q & 1)*8;
                    uint32_t off = (uint32_t)(row*FP + col) * 2;
                    uint32_t tmp[4];
                    ldm4(base + FKHI*2 + off, tmp);
                    kh[bt*2][0]=tmp[0]; kh[bt*2][1]=tmp[1];
                    kh[bt*2+1][0]=tmp[2]; kh[bt*2+1][1]=tmp[3];
                    ldm4(base + FKLO*2 + off, tmp);
                    kl[bt*2][0]=tmp[0]; kl[bt*2][1]=tmp[1];
                    kl[bt*2+1][0]=tmp[2]; kl[bt*2+1][1]=tmp[3];
                }
#pragma unroll
                for (int nt = 0; nt < 4; nt++) {
                    mma16816(sacc[nt], qhi[ks], kh[nt]);
                    mma16816(sacc[nt], qhi[ks], kl[nt]);
                    mma16816(sacc[nt], qlo[ks], kh[nt]);
                }
            }

            // ---- add BD (exp2 domain), online softmax
            float ml0 = -1e30f, ml1 = -1e30f;
#pragma unroll
            for (int nt = 0; nt < 4; nt++)
#pragma unroll
                for (int e = 0; e < 4; e++) {
                    float sv = fmaf(bd[nt][e], CSC, sacc[nt][e]);
                    sacc[nt][e] = sv;
                    if (e < 2) ml0 = fmaxf(ml0, sv); else ml1 = fmaxf(ml1, sv);
                }
            ml0 = fmaxf(ml0, __shfl_xor_sync(0xFFFFFFFFu, ml0, 1));
            ml0 = fmaxf(ml0, __shfl_xor_sync(0xFFFFFFFFu, ml0, 2));
            ml1 = fmaxf(ml1, __shfl_xor_sync(0xFFFFFFFFu, ml1, 1));
            ml1 = fmaxf(ml1, __shfl_xor_sync(0xFFFFFFFFu, ml1, 2));

            float mn0 = fmaxf(m0, ml0), mn1 = fmaxf(m1, ml1);
            float f0 = ex2f(m0 - mn0), f1 = ex2f(m1 - mn1);
            m0 = mn0; m1 = mn1;

            float ls0 = 0.f, ls1 = 0.f;
#pragma unroll
            for (int nt = 0; nt < 4; nt++) {
                float p0 = ex2f(sacc[nt][0] - m0);
                float p1 = ex2f(sacc[nt][1] - m0);
                float p2 = ex2f(sacc[nt][2] - m1);
                float p3 = ex2f(sacc[nt][3] - m1);
                sacc[nt][0] = p0; sacc[nt][1] = p1; sacc[nt][2] = p2; sacc[nt][3] = p3;
                ls0 += p0 + p1;  ls1 += p2 + p3;
            }
            ls0 += __shfl_xor_sync(0xFFFFFFFFu, ls0, 1);
            ls0 += __shfl_xor_sync(0xFFFFFFFFu, ls0, 2);
            ls1 += __shfl_xor_sync(0xFFFFFFFFu, ls1, 1);
            ls1 += __shfl_xor_sync(0xFFFFFFFFu, ls1, 2);
            l0 = l0 * f0 + ls0;
            l1 = l1 * f1 + ls1;

#pragma unroll
            for (int dt = 0; dt < 8; dt++) {
                pacc[dt][0] *= f0; pacc[dt][1] *= f0;
                pacc[dt][2] *= f1; pacc[dt][3] *= f1;
            }

            // ---- pack P (C-frag pair -> A-frag)
            uint32_t phi[2][4], plo[2][4];
#pragma unroll
            for (int ks = 0; ks < 2; ks++) {
                cvt2(sacc[2*ks][0],   sacc[2*ks][1],   phi[ks][0], plo[ks][0]);
                cvt2(sacc[2*ks][2],   sacc[2*ks][3],   phi[ks][1], plo[ks][1]);
                cvt2(sacc[2*ks+1][0], sacc[2*ks+1][1], phi[ks][2], plo[ks][2]);
                cvt2(sacc[2*ks+1][2], sacc[2*ks+1][3], phi[ks][3], plo[ks][3]);
            }

            // ---- pacc += P @ V  (B-frags via ldmatrix.trans of row-major V)
#pragma unroll
            for (int ks = 0; ks < 2; ks++) {
                uint32_t vh[8][2], vl[8][2];
#pragma unroll
                for (int dt2 = 0; dt2 < 4; dt2++) {
                    int krow = (sub << 5) + ks*16 + (lane & 7) + ((lane >> 3) & 1)*8;
                    int ncol = dt2*16 + ((lane >> 4) << 3);
                    uint32_t off = (uint32_t)(krow*FP + ncol) * 2;
                    uint32_t tmp[4];
                    ldm4t(base + FVHI*2 + off, tmp);
                    vh[dt2*2][0]=tmp[0]; vh[dt2*2][1]=tmp[1];
                    vh[dt2*2+1][0]=tmp[2]; vh[dt2*2+1][1]=tmp[3];
                    ldm4t(base + FVLO*2 + off, tmp);
                    vl[dt2*2][0]=tmp[0]; vl[dt2*2][1]=tmp[1];
                    vl[dt2*2+1][0]=tmp[2]; vl[dt2*2+1][1]=tmp[3];
                }
#pragma unroll
                for (int dt = 0; dt < 8; dt++) {
                    mma16816(pacc[dt], phi[ks], vh[dt]);
                    mma16816(pacc[dt], phi[ks], vl[dt]);
                    mma16816(pacc[dt], plo[ks], vh[dt]);
                }
            }
        }
        __syncthreads();
    }

    // ---- normalize & write out (fp32 AO)
    float inv0 = 1.f / l0, inv1 = 1.f / l1;
    float* Og = g_AO + (size_t)b*Sn*Dn + h*DHn;
#pragma unroll
    for (int dt = 0; dt < 8; dt++) {
        int d = dt*8 + 2*qq;
        float2 o0 = make_float2(pacc[dt][0]*inv0, pacc[dt][1]*inv0);
        float2 o1 = make_float2(pacc[dt][2]*inv1, pacc[dt][3]*inv1);
        *(float2*)(Og + (size_t)i_r  * Dn + d) = o0;
        *(float2*)(Og + (size_t)i_r8 * Dn + d) = o1;
    }
}

// ---------------------------------------------------------------------------
// Launch
// ---------------------------------------------------------------------------
extern "C" void kernel_launch(void* const* d_in, const int* in_sizes, int n_in,
                              void* d_out, int out_size)
{
    const float* x   = (const float*)d_in[0];
    const float* pos = (const float*)d_in[1];
    const float* Wq  = (const float*)d_in[2];
    const float* bq  = (const float*)d_in[3];
    const float* Wk  = (const float*)d_in[4];
    const float* bk  = (const float*)d_in[5];
    const float* Wv  = (const float*)d_in[6];
    const float* bv  = (const float*)d_in[7];
    const float* Wo  = (const float*)d_in[8];
    const float* bo  = (const float*)d_in[9];
    const float* Wkr = (const float*)d_in[10];
    const float* bkr = (const float*)d_in[11];
    const float* u   = (const float*)d_in[12];
    // d_in[13] (v) unused: GH term is per-row constant -> softmax-invariant.

    cudaFuncSetAttribute(proj_fused,  cudaFuncAttributeMaxDynamicSharedMemorySize, GEMM_SMEM);
    cudaFuncSetAttribute(mma_gemm_wo, cudaFuncAttributeMaxDynamicSharedMemorySize, GEMM_SMEM);
    cudaFuncSetAttribute(mma_gemm_t,  cudaFuncAttributeMaxDynamicSharedMemorySize, TSMEM);
    cudaFuncSetAttribute(flash_mma,   cudaFuncAttributeMaxDynamicSharedMemorySize, FLASH_SMEM);
    cudaFuncSetAttribute(flash_mma,   cudaFuncAttributePreferredSharedMemoryCarveout, 100);

    dim3 thr(256);
    proj_fused<<<dim3(Dn/128, (Bn*Sn)/128, 4), thr, GEMM_SMEM>>>(
        x, pos, Wq, bq, Wk, bk, Wv, bv, Wkr, bkr);
    mma_gemm_t<<<dim3(Sn/128, Sn/128, BHn), thr, TSMEM>>>();
    flash_mma<<<dim3(Sn/128, BHn), thr, FLASH_SMEM>>>(u);
    mma_gemm_wo<<<dim3(Dn/128, (Bn*Sn)/128), thr, GEMM_SMEM>>>(Wo, bo, (float*)d_out);
}